// round 9
// baseline (speedup 1.0000x reference)
#include <cuda_runtime.h>
#include <math.h>
#include <stdint.h>

// ---------------- problem constants ----------------
#define N_GT   100000
#define N_AG   20000
#define E_GT   640000
#define E_COMM 320000
#define D_GT   32
#define D_AG   64
#define VIS    64
#define COMM   128
#define MSG    64
#define OUTD   5
#define LRELU  0.2f

// ---------------- scratch (device globals; no runtime alloc) ----------------
// fsall row layout (stride 256 floats = 1KB): [0:64) fs1, [64:192) fs2, [192:196) el1, [196:200) el2
__device__ float g_fsall[N_GT * 256];
__device__ float g_bsrc[32 * 256];           // packed B for the src projection GEMM
__device__ float g_h[N_AG * COMM];           // h ping
__device__ float g_h2[N_AG * COMM];          // h pong
__device__ float g_y[N_AG * MSG];            // mailbox mean
__device__ float g_hidden[N_AG * 128];
__device__ float g_m[N_AG * MSG];
__device__ int   g_gt_rowptr[N_AG + 1];
__device__ int   g_cm_rowptr[N_AG + 1];
__device__ int   g_gt_cursor[N_AG];
__device__ int   g_cm_cursor[N_AG];
__device__ int   g_gt_srcs[E_GT];
__device__ int   g_cm_srcs[E_COMM];
__device__ float g_wa1r[64 * 4];
__device__ float g_wa2r[128 * 4];

__device__ __forceinline__ float leaky(float x) { return x >= 0.f ? x : LRELU * x; }
__device__ __forceinline__ float sigmoidf(float x) { return 1.f / (1.f + __expf(-x)); }
__device__ __forceinline__ float warp_sum(float p) {
#pragma unroll
    for (int o = 16; o > 0; o >>= 1) p += __shfl_xor_sync(0xffffffffu, p, o);
    return p;
}
__device__ __forceinline__ uint32_t f2tf32(float x) {
    uint32_t r;
    asm("cvt.rna.tf32.f32 %0, %1;" : "=r"(r) : "f"(x));
    return r;
}
__device__ __forceinline__ void mma_tf32(float* c, const uint32_t* a, uint32_t b0, uint32_t b1) {
    asm volatile(
        "mma.sync.aligned.m16n8k8.row.col.f32.tf32.tf32.f32 "
        "{%0,%1,%2,%3},{%4,%5,%6,%7},{%8,%9},{%0,%1,%2,%3};"
        : "+f"(c[0]), "+f"(c[1]), "+f"(c[2]), "+f"(c[3])
        : "r"(a[0]), "r"(a[1]), "r"(a[2]), "r"(a[3]), "r"(b0), "r"(b1));
}

// ---------------- init: fold attn vectors + pack bsrc + zero rowptrs (one launch) ----------------
__global__ void k_init(const float* __restrict__ w1s, const float* __restrict__ w1d,
                       const float* __restrict__ a1l, const float* __restrict__ a1r,
                       const float* __restrict__ w2s, const float* __restrict__ w2d,
                       const float* __restrict__ a2l, const float* __restrict__ a2r) {
    int i = blockIdx.x * blockDim.x + threadIdx.x;
    if (i < 8192) {
        int k = i >> 8, c = i & 255;
        float v = 0.f;
        if (c < 64)       v = w1s[k * 64 + c];
        else if (c < 192) v = w2s[k * 128 + (c - 64)];
        else if (c < 196) {
            int h = c - 192; float s = 0.f;
            for (int d = 0; d < 16; d++) s += w1s[k * 64 + h * 16 + d] * a1l[h * 16 + d];
            v = s;
        } else if (c < 200) {
            int h = c - 196; float s = 0.f;
            for (int d = 0; d < 32; d++) s += w2s[k * 128 + h * 32 + d] * a2l[h * 32 + d];
            v = s;
        }
        g_bsrc[i] = v;
    } else if (i < 8448) {
        int u = i - 8192; int k = u >> 2, h = u & 3; float s = 0.f;
        for (int d = 0; d < 16; d++) s += w1d[k * 64 + h * 16 + d] * a1r[h * 16 + d];
        g_wa1r[u] = s;
    } else if (i < 8960) {
        int u = i - 8448; int k = u >> 2, h = u & 3; float s = 0.f;
        for (int d = 0; d < 32; d++) s += w2d[k * 128 + h * 32 + d] * a2r[h * 32 + d];
        g_wa2r[u] = s;
    } else {
        int u = i - 8960;
        if (u <= N_AG) g_gt_rowptr[u] = 0;
        else {
            u -= (N_AG + 1);
            if (u <= N_AG) g_cm_rowptr[u] = 0;
        }
    }
}

// ---------------- CSR build ----------------
__global__ void k_hist(const int* __restrict__ gtd, const int* __restrict__ cmd) {
    int i = blockIdx.x * blockDim.x + threadIdx.x;
    if (i < E_GT / 4) {
        int4 d = ((const int4*)gtd)[i];
        atomicAdd(&g_gt_rowptr[d.x + 1], 1);
        atomicAdd(&g_gt_rowptr[d.y + 1], 1);
        atomicAdd(&g_gt_rowptr[d.z + 1], 1);
        atomicAdd(&g_gt_rowptr[d.w + 1], 1);
    }
    if (i < E_COMM / 4) {
        int4 d = ((const int4*)cmd)[i];
        atomicAdd(&g_cm_rowptr[d.x + 1], 1);
        atomicAdd(&g_cm_rowptr[d.y + 1], 1);
        atomicAdd(&g_cm_rowptr[d.z + 1], 1);
        atomicAdd(&g_cm_rowptr[d.w + 1], 1);
    }
}

__global__ void k_scan() {  // <<<2,1024>>>: block 0 = gt, block 1 = comm. Also inits cursor = rowptr.
    __shared__ int wsum[32];
    int* a   = (blockIdx.x == 0) ? g_gt_rowptr : g_cm_rowptr;
    int* cur = (blockIdx.x == 0) ? g_gt_cursor : g_cm_cursor;
    const int n = N_AG;
    const int PER = 20;
    int t = threadIdx.x, lane = t & 31, wid = t >> 5;
    int base = 1 + t * PER;
    int loc[PER]; int s = 0;
#pragma unroll
    for (int j = 0; j < PER; j++) {
        int idx = base + j;
        int v = (idx <= n) ? a[idx] : 0;
        s += v; loc[j] = s;
    }
    int sc = s;
#pragma unroll
    for (int o = 1; o < 32; o <<= 1) {
        int v = __shfl_up_sync(0xffffffffu, sc, o);
        if (lane >= o) sc += v;
    }
    if (lane == 31) wsum[wid] = sc;
    __syncthreads();
    if (wid == 0) {
        int v = wsum[lane];
#pragma unroll
        for (int o = 1; o < 32; o <<= 1) {
            int u = __shfl_up_sync(0xffffffffu, v, o);
            if (lane >= o) v += u;
        }
        wsum[lane] = v;
    }
    __syncthreads();
    int pre = (sc - s) + (wid > 0 ? wsum[wid - 1] : 0);
#pragma unroll
    for (int j = 0; j < PER; j++) {
        int idx = base + j;
        if (idx <= n) {
            int val = loc[j] + pre;
            a[idx] = val;
            if (idx < n) cur[idx] = val;
        }
    }
    if (t == 0) cur[0] = 0;
}

__global__ void k_scatter(const int* __restrict__ gts, const int* __restrict__ gtd,
                          const int* __restrict__ cms, const int* __restrict__ cmd) {
    int i = blockIdx.x * blockDim.x + threadIdx.x;
    if (i < E_GT / 4) {
        int4 s = ((const int4*)gts)[i];
        int4 d = ((const int4*)gtd)[i];
        g_gt_srcs[atomicAdd(&g_gt_cursor[d.x], 1)] = s.x;
        g_gt_srcs[atomicAdd(&g_gt_cursor[d.y], 1)] = s.y;
        g_gt_srcs[atomicAdd(&g_gt_cursor[d.z], 1)] = s.z;
        g_gt_srcs[atomicAdd(&g_gt_cursor[d.w], 1)] = s.w;
    }
    if (i < E_COMM / 4) {
        int4 s = ((const int4*)cms)[i];
        int4 d = ((const int4*)cmd)[i];
        g_cm_srcs[atomicAdd(&g_cm_cursor[d.x], 1)] = s.x;
        g_cm_srcs[atomicAdd(&g_cm_cursor[d.y], 1)] = s.y;
        g_cm_srcs[atomicAdd(&g_cm_cursor[d.z], 1)] = s.z;
        g_cm_srcs[atomicAdd(&g_cm_cursor[d.w], 1)] = s.w;
    }
}

// ---------------- src projection GEMM (split-tf32, fp32-class accuracy) ----------------
__global__ void __launch_bounds__(256) k_srcmma(const float* __restrict__ feat) {
    constexpr int ALD = 36, BLD = 72;
    __shared__ uint32_t Ah[64 * ALD], Al[64 * ALD];
    __shared__ uint32_t Bh[32 * BLD], Bl[32 * BLD];
    int tid = threadIdx.x, lane = tid & 31, warp = tid >> 5;
    int g = lane >> 2, t4 = lane & 3;
    int wrow = (warp >> 1) * 16, wcol = (warp & 1) * 32;
    int bm = blockIdx.y * 64, bn = blockIdx.x * 64;

    float acc[4][4];
#pragma unroll
    for (int nt = 0; nt < 4; nt++)
#pragma unroll
        for (int q = 0; q < 4; q++) acc[nt][q] = 0.f;

#pragma unroll
    for (int it = 0; it < 2; it++) {
        int r = it * 32 + (tid >> 3);
        int c = (tid & 7) * 4;
        int gr = bm + r;
        float4 v = make_float4(0.f, 0.f, 0.f, 0.f);
        if (gr < N_GT) v = *(const float4*)(feat + (size_t)gr * 32 + c);
        uint32_t hx = f2tf32(v.x), hy = f2tf32(v.y), hz = f2tf32(v.z), hw = f2tf32(v.w);
        *(uint4*)&Ah[r * ALD + c] = make_uint4(hx, hy, hz, hw);
        *(uint4*)&Al[r * ALD + c] = make_uint4(f2tf32(v.x - __uint_as_float(hx)),
                                               f2tf32(v.y - __uint_as_float(hy)),
                                               f2tf32(v.z - __uint_as_float(hz)),
                                               f2tf32(v.w - __uint_as_float(hw)));
    }
#pragma unroll
    for (int it = 0; it < 2; it++) {
        int r = it * 16 + (tid >> 4);
        int c = (tid & 15) * 4;
        float4 v = *(const float4*)(g_bsrc + r * 256 + bn + c);
        uint32_t hx = f2tf32(v.x), hy = f2tf32(v.y), hz = f2tf32(v.z), hw = f2tf32(v.w);
        *(uint4*)&Bh[r * BLD + c] = make_uint4(hx, hy, hz, hw);
        *(uint4*)&Bl[r * BLD + c] = make_uint4(f2tf32(v.x - __uint_as_float(hx)),
                                               f2tf32(v.y - __uint_as_float(hy)),
                                               f2tf32(v.z - __uint_as_float(hz)),
                                               f2tf32(v.w - __uint_as_float(hw)));
    }
    __syncthreads();

#pragma unroll
    for (int ks = 0; ks < 4; ks++) {
        int kk = ks * 8;
        uint32_t ah[4], al[4];
        ah[0] = Ah[(wrow + g) * ALD + kk + t4];
        ah[1] = Ah[(wrow + g + 8) * ALD + kk + t4];
        ah[2] = Ah[(wrow + g) * ALD + kk + t4 + 4];
        ah[3] = Ah[(wrow + g + 8) * ALD + kk + t4 + 4];
        al[0] = Al[(wrow + g) * ALD + kk + t4];
        al[1] = Al[(wrow + g + 8) * ALD + kk + t4];
        al[2] = Al[(wrow + g) * ALD + kk + t4 + 4];
        al[3] = Al[(wrow + g + 8) * ALD + kk + t4 + 4];
#pragma unroll
        for (int nt = 0; nt < 4; nt++) {
            int n0 = wcol + nt * 8;
            uint32_t bh0 = Bh[(kk + t4) * BLD + n0 + g];
            uint32_t bh1 = Bh[(kk + t4 + 4) * BLD + n0 + g];
            uint32_t bl0 = Bl[(kk + t4) * BLD + n0 + g];
            uint32_t bl1 = Bl[(kk + t4 + 4) * BLD + n0 + g];
            mma_tf32(acc[nt], ah, bh0, bh1);
            mma_tf32(acc[nt], ah, bl0, bl1);
            mma_tf32(acc[nt], al, bh0, bh1);
        }
    }

#pragma unroll
    for (int nt = 0; nt < 4; nt++) {
        int rr = bm + wrow + g;
        int cc = bn + wcol + nt * 8 + 2 * t4;
        if (cc < 200) {
            if (rr < N_GT)
                *(float2*)(g_fsall + (size_t)rr * 256 + cc) = make_float2(acc[nt][0], acc[nt][1]);
            if (rr + 8 < N_GT)
                *(float2*)(g_fsall + (size_t)(rr + 8) * 256 + cc) = make_float2(acc[nt][2], acc[nt][3]);
        }
    }
}

// ---------------- merged GAT: both layers, one edge pass each ----------------
__global__ void k_gat(const float* __restrict__ fa_, const float* __restrict__ b1,
                      const float* __restrict__ b2) {
    int gid = blockIdx.x * blockDim.x + threadIdx.x;
    int n = gid >> 5;
    int lane = threadIdx.x & 31;
    if (n >= N_AG) return;
    float fa0 = fa_[n * 64 + lane], fa1 = fa_[n * 64 + lane + 32];
    bool hi = (lane >= 16);
    int beg = g_gt_rowptr[n], end = g_gt_rowptr[n + 1];

    // ---- layer 1 ----
    float er0 = warp_sum(fa0 * g_wa1r[lane * 4 + 0] + fa1 * g_wa1r[(lane + 32) * 4 + 0]);
    float er1 = warp_sum(fa0 * g_wa1r[lane * 4 + 1] + fa1 * g_wa1r[(lane + 32) * 4 + 1]);
    float er2 = warp_sum(fa0 * g_wa1r[lane * 4 + 2] + fa1 * g_wa1r[(lane + 32) * 4 + 2]);
    float er3 = warp_sum(fa0 * g_wa1r[lane * 4 + 3] + fa1 * g_wa1r[(lane + 32) * 4 + 3]);
    float acc0 = 0.f, acc1 = 0.f, d0 = 0.f, d1 = 0.f, d2 = 0.f, d3 = 0.f;
    for (int base = beg; base < end; base += 32) {
        int i = base + lane;
        int cnt = min(32, end - base);
        int s = 0; float p0 = 0.f, p1 = 0.f, p2 = 0.f, p3 = 0.f;
        if (i < end) {
            s = g_gt_srcs[i];
            float4 e = *(const float4*)(g_fsall + (size_t)s * 256 + 192);
            p0 = __expf(leaky(e.x + er0));
            p1 = __expf(leaky(e.y + er1));
            p2 = __expf(leaky(e.z + er2));
            p3 = __expf(leaky(e.w + er3));
            d0 += p0; d1 += p1; d2 += p2; d3 += p3;
        }
        for (int j = 0; j < cnt; j++) {
            int sj   = __shfl_sync(0xffffffffu, s, j);
            float q0 = __shfl_sync(0xffffffffu, p0, j);
            float q1 = __shfl_sync(0xffffffffu, p1, j);
            float q2 = __shfl_sync(0xffffffffu, p2, j);
            float q3 = __shfl_sync(0xffffffffu, p3, j);
            const float* fr = g_fsall + (size_t)sj * 256;
            acc0 += fr[lane] * (hi ? q1 : q0);
            acc1 += fr[lane + 32] * (hi ? q3 : q2);
        }
    }
    d0 = warp_sum(d0); d1 = warp_sum(d1); d2 = warp_sum(d2); d3 = warp_sum(d3);
    float dlo = hi ? d1 : d0;
    float dhi = hi ? d3 : d2;
    float hv0 = fmaxf((dlo > 0.f ? acc0 / dlo : 0.f) + fa0 + b1[lane], 0.f);
    float hv1 = fmaxf((dhi > 0.f ? acc1 / dhi : 0.f) + fa1 + b1[lane + 32], 0.f);

    // ---- layer 2 ----
    float f0 = warp_sum(hv0 * g_wa2r[lane * 4 + 0] + hv1 * g_wa2r[(lane + 32) * 4 + 0] +
                        fa0 * g_wa2r[(lane + 64) * 4 + 0] + fa1 * g_wa2r[(lane + 96) * 4 + 0]);
    float f1 = warp_sum(hv0 * g_wa2r[lane * 4 + 1] + hv1 * g_wa2r[(lane + 32) * 4 + 1] +
                        fa0 * g_wa2r[(lane + 64) * 4 + 1] + fa1 * g_wa2r[(lane + 96) * 4 + 1]);
    float f2 = warp_sum(hv0 * g_wa2r[lane * 4 + 2] + hv1 * g_wa2r[(lane + 32) * 4 + 2] +
                        fa0 * g_wa2r[(lane + 64) * 4 + 2] + fa1 * g_wa2r[(lane + 96) * 4 + 2]);
    float f3 = warp_sum(hv0 * g_wa2r[lane * 4 + 3] + hv1 * g_wa2r[(lane + 32) * 4 + 3] +
                        fa0 * g_wa2r[(lane + 64) * 4 + 3] + fa1 * g_wa2r[(lane + 96) * 4 + 3]);
    float A0 = 0.f, A1 = 0.f, A2 = 0.f, A3 = 0.f;
    float e0 = 0.f, e1 = 0.f, e2 = 0.f, e3 = 0.f;
    for (int base = beg; base < end; base += 32) {
        int i = base + lane;
        int cnt = min(32, end - base);
        int s = 0; float p0 = 0.f, p1 = 0.f, p2 = 0.f, p3 = 0.f;
        if (i < end) {
            s = g_gt_srcs[i];
            float4 e = *(const float4*)(g_fsall + (size_t)s * 256 + 196);
            p0 = __expf(leaky(e.x + f0));
            p1 = __expf(leaky(e.y + f1));
            p2 = __expf(leaky(e.z + f2));
            p3 = __expf(leaky(e.w + f3));
            e0 += p0; e1 += p1; e2 += p2; e3 += p3;
        }
        for (int j = 0; j < cnt; j++) {
            int sj   = __shfl_sync(0xffffffffu, s, j);
            float q0 = __shfl_sync(0xffffffffu, p0, j);
            float q1 = __shfl_sync(0xffffffffu, p1, j);
            float q2 = __shfl_sync(0xffffffffu, p2, j);
            float q3 = __shfl_sync(0xffffffffu, p3, j);
            const float* fr = g_fsall + (size_t)sj * 256 + 64;
            A0 += fr[lane] * q0;
            A1 += fr[lane + 32] * q1;
            A2 += fr[lane + 64] * q2;
            A3 += fr[lane + 96] * q3;
        }
    }
    e0 = warp_sum(e0); e1 = warp_sum(e1); e2 = warp_sum(e2); e3 = warp_sum(e3);
    float r0 = e0 > 0.f ? A0 / e0 : 0.f;
    float r1 = e1 > 0.f ? A1 / e1 : 0.f;
    float r2 = e2 > 0.f ? A2 / e2 : 0.f;
    float r3 = e3 > 0.f ? A3 / e3 : 0.f;
    g_h[n * 128 + lane]      = fmaxf(r0 + hv0 + b2[lane], 0.f);
    g_h[n * 128 + lane + 32] = fmaxf(r1 + hv1 + b2[lane + 32], 0.f);
    g_h[n * 128 + lane + 64] = fmaxf(r2 + fa0 + b2[lane + 64], 0.f);
    g_h[n * 128 + lane + 96] = fmaxf(r3 + fa1 + b2[lane + 96], 0.f);
}

// ---------------- TF32 tensor-core GEMM (enc layers) ----------------
template <int BN, int RELU>
__global__ void __launch_bounds__(256)
k_mma(const float* __restrict__ A, const float* __restrict__ B,
      const float* __restrict__ bias, float* __restrict__ C,
      int M, int N, int K) {
    constexpr int WN  = BN / 64;
    constexpr int WM  = 8 / WN;
    constexpr int WTM = 128 / WM;
    constexpr int MT  = WTM / 16;
    constexpr int ALD = 36;
    constexpr int BLD = BN + 8;

    __shared__ uint32_t As[128 * ALD];
    __shared__ uint32_t Bs[32 * BLD];

    const int tid  = threadIdx.x;
    const int lane = tid & 31;
    const int warp = tid >> 5;
    const int g    = lane >> 2;
    const int t4   = lane & 3;
    const int wm   = warp / WN;
    const int wn   = warp % WN;
    const int wrow = wm * WTM;
    const int wcol = wn * 64;
    const int bm   = blockIdx.y * 128;
    const int bn   = blockIdx.x * BN;

    float acc[MT][8][4];
#pragma unroll
    for (int mt = 0; mt < MT; mt++)
#pragma unroll
        for (int nt = 0; nt < 8; nt++)
#pragma unroll
            for (int q = 0; q < 4; q++) acc[mt][nt][q] = 0.f;

    for (int k0 = 0; k0 < K; k0 += 32) {
#pragma unroll
        for (int it = 0; it < 4; it++) {
            int r = it * 32 + (tid >> 3);
            int c = (tid & 7) * 4;
            int gr = bm + r;
            float4 v = make_float4(0.f, 0.f, 0.f, 0.f);
            if (gr < M) v = *(const float4*)(A + (size_t)gr * K + k0 + c);
            uint4 u;
            u.x = f2tf32(v.x); u.y = f2tf32(v.y); u.z = f2tf32(v.z); u.w = f2tf32(v.w);
            *(uint4*)&As[r * ALD + c] = u;
        }
        if (BN == 128) {
#pragma unroll
            for (int it = 0; it < 4; it++) {
                int r = it * 8 + (tid >> 5);
                int c = (tid & 31) * 4;
                float4 v = *(const float4*)(B + (size_t)(k0 + r) * N + bn + c);
                uint4 u;
                u.x = f2tf32(v.x); u.y = f2tf32(v.y); u.z = f2tf32(v.z); u.w = f2tf32(v.w);
                *(uint4*)&Bs[r * BLD + c] = u;
            }
        } else {
#pragma unroll
            for (int it = 0; it < 2; it++) {
                int r = it * 16 + (tid >> 4);
                int c = (tid & 15) * 4;
                float4 v = *(const float4*)(B + (size_t)(k0 + r) * N + bn + c);
                uint4 u;
                u.x = f2tf32(v.x); u.y = f2tf32(v.y); u.z = f2tf32(v.z); u.w = f2tf32(v.w);
                *(uint4*)&Bs[r * BLD + c] = u;
            }
        }
        __syncthreads();

#pragma unroll
        for (int ks = 0; ks < 4; ks++) {
            int kk = ks * 8;
            uint32_t a[MT][4];
#pragma unroll
            for (int mt = 0; mt < MT; mt++) {
                int r = wrow + mt * 16;
                a[mt][0] = As[(r + g) * ALD + kk + t4];
                a[mt][1] = As[(r + g + 8) * ALD + kk + t4];
                a[mt][2] = As[(r + g) * ALD + kk + t4 + 4];
                a[mt][3] = As[(r + g + 8) * ALD + kk + t4 + 4];
            }
#pragma unroll
            for (int nt = 0; nt < 8; nt++) {
                int n0 = wcol + nt * 8;
                uint32_t b0 = Bs[(kk + t4) * BLD + n0 + g];
                uint32_t b1 = Bs[(kk + t4 + 4) * BLD + n0 + g];
#pragma unroll
                for (int mt = 0; mt < MT; mt++)
                    mma_tf32(acc[mt][nt], a[mt], b0, b1);
            }
        }
        __syncthreads();
    }

#pragma unroll
    for (int mt = 0; mt < MT; mt++) {
#pragma unroll
        for (int nt = 0; nt < 8; nt++) {
            int rr = bm + wrow + mt * 16 + g;
            int cc = bn + wcol + nt * 8 + 2 * t4;
            float bb0 = bias[cc], bb1 = bias[cc + 1];
            if (rr < M) {
                float v0 = acc[mt][nt][0] + bb0;
                float v1 = acc[mt][nt][1] + bb1;
                if (RELU) { v0 = fmaxf(v0, 0.f); v1 = fmaxf(v1, 0.f); }
                *(float2*)(C + (size_t)rr * N + cc) = make_float2(v0, v1);
            }
            if (rr + 8 < M) {
                float v0 = acc[mt][nt][2] + bb0;
                float v1 = acc[mt][nt][3] + bb1;
                if (RELU) { v0 = fmaxf(v0, 0.f); v1 = fmaxf(v1, 0.f); }
                *(float2*)(C + (size_t)(rr + 8) * N + cc) = make_float2(v0, v1);
            }
        }
    }
}

// ---------------- comm mailbox mean -> g_y ----------------
__global__ void k_yagg() {
    int gid = blockIdx.x * blockDim.x + threadIdx.x;
    int n = gid >> 5;
    int lane = threadIdx.x & 31;
    if (n >= N_AG) return;
    int beg = g_cm_rowptr[n], end = g_cm_rowptr[n + 1];
    float a0 = 0.f, a1 = 0.f;
    int i = beg;
    for (; i + 1 < end; i += 2) {
        int s0 = g_cm_srcs[i], s1 = g_cm_srcs[i + 1];
        a0 += g_m[s0 * 64 + lane] + g_m[s1 * 64 + lane];
        a1 += g_m[s0 * 64 + lane + 32] + g_m[s1 * 64 + lane + 32];
    }
    if (i < end) {
        int s = g_cm_srcs[i];
        a0 += g_m[s * 64 + lane];
        a1 += g_m[s * 64 + lane + 32];
    }
    float inv = 1.f / fmaxf((float)(end - beg), 1.f);
    g_y[n * 64 + lane] = a0 * inv;
    g_y[n * 64 + lane + 32] = a1 * inv;
}

// ---------------- fused GRU: gi GEMM (K=192) + gh GEMM (K=128) + gate math ----------------
// Block: 128 rows x gate-aligned cols {cslab..cslab+31} in each of r/z/n gate groups.
// Grid (4, 157). Warp layout 4(M) x 2(N); warp tile 32 rows x (2x8 cols per gate x 3 gates).
// nt = gate*2 + p: col = gate*128 + cslab + wn*16 + p*8 + frag-col. Triplets land in one thread.
__global__ void __launch_bounds__(256) k_gruf(
    const float* __restrict__ hA,        // x[:,0:128] source (h part), stride 128
    const float* __restrict__ hprev,     // GRU state, stride 128
    const float* __restrict__ w_ih,      // [192,384]
    const float* __restrict__ w_hh,      // [128,384]
    const float* __restrict__ b_ih, const float* __restrict__ b_hh,
    float* __restrict__ hout,            // new h, stride 128
    float* __restrict__ out, int write_zz)
{
    constexpr int ALD = 20, BLD = 104;
    __shared__ uint32_t As[128 * ALD];
    __shared__ uint32_t Bs[16 * BLD];
    const int tid = threadIdx.x, lane = tid & 31, warp = tid >> 5;
    const int g = lane >> 2, t4 = lane & 3;
    const int wm = warp >> 1, wn = warp & 1;
    const int wrow = wm * 32;
    const int bm = blockIdx.y * 128;
    const int cslab = blockIdx.x * 32;

    float ai[2][6][4], ah[2][6][4];
#pragma unroll
    for (int mt = 0; mt < 2; mt++)
#pragma unroll
        for (int nt = 0; nt < 6; nt++)
#pragma unroll
            for (int q = 0; q < 4; q++) { ai[mt][nt][q] = 0.f; ah[mt][nt][q] = 0.f; }

    const int arow = tid >> 1;
    const int acol = (tid & 1) * 8;

    // ======== phase A: x @ w_ih, K = 192 (x = [hA | y]) ========
    for (int k0 = 0; k0 < 192; k0 += 16) {
        int grow = bm + arow;
        const float* asrc;
        int astride, abase;
        if (k0 < 128) { asrc = hA; astride = 128; abase = k0; }
        else          { asrc = g_y; astride = 64; abase = k0 - 128; }
#pragma unroll
        for (int it = 0; it < 2; it++) {
            float4 v = make_float4(0.f, 0.f, 0.f, 0.f);
            if (grow < N_AG) v = *(const float4*)(asrc + (size_t)grow * astride + abase + acol + it * 4);
            uint4 u;
            u.x = f2tf32(v.x); u.y = f2tf32(v.y); u.z = f2tf32(v.z); u.w = f2tf32(v.w);
            *(uint4*)&As[arow * ALD + acol + it * 4] = u;
        }
        for (int idx = tid; idx < 16 * 24; idx += 256) {
            int r = idx / 24, j0 = (idx % 24) * 4;
            int gcol = ((j0 >> 5) << 7) + cslab + (j0 & 31);
            float4 v = *(const float4*)(w_ih + (size_t)(k0 + r) * 384 + gcol);
            uint4 u;
            u.x = f2tf32(v.x); u.y = f2tf32(v.y); u.z = f2tf32(v.z); u.w = f2tf32(v.w);
            *(uint4*)&Bs[r * BLD + j0] = u;
        }
        __syncthreads();
#pragma unroll
        for (int ks = 0; ks < 2; ks++) {
            int kk = ks * 8;
            uint32_t afr[2][4];
#pragma unroll
            for (int mt = 0; mt < 2; mt++) {
                int rr = wrow + mt * 16;
                afr[mt][0] = As[(rr + g) * ALD + kk + t4];
                afr[mt][1] = As[(rr + g + 8) * ALD + kk + t4];
                afr[mt][2] = As[(rr + g) * ALD + kk + t4 + 4];
                afr[mt][3] = As[(rr + g + 8) * ALD + kk + t4 + 4];
            }
#pragma unroll
            for (int nt = 0; nt < 6; nt++) {
                int j = ((nt >> 1) << 5) + wn * 16 + ((nt & 1) << 3) + g;
                uint32_t b0 = Bs[(kk + t4) * BLD + j];
                uint32_t b1 = Bs[(kk + t4 + 4) * BLD + j];
#pragma unroll
                for (int mt = 0; mt < 2; mt++)
                    mma_tf32(ai[mt][nt], afr[mt], b0, b1);
            }
        }
        __syncthreads();
    }

    // ======== phase B: hprev @ w_hh, K = 128 ========
    for (int k0 = 0; k0 < 128; k0 += 16) {
        int grow = bm + arow;
#pragma unroll
        for (int it = 0; it < 2; it++) {
            float4 v = make_float4(0.f, 0.f, 0.f, 0.f);
            if (grow < N_AG) v = *(const float4*)(hprev + (size_t)grow * 128 + k0 + acol + it * 4);
            uint4 u;
            u.x = f2tf32(v.x); u.y = f2tf32(v.y); u.z = f2tf32(v.z); u.w = f2tf32(v.w);
            *(uint4*)&As[arow * ALD + acol + it * 4] = u;
        }
        for (int idx = tid; idx < 16 * 24; idx += 256) {
            int r = idx / 24, j0 = (idx % 24) * 4;
            int gcol = ((j0 >> 5) << 7) + cslab + (j0 & 31);
            float4 v = *(const float4*)(w_hh + (size_t)(k0 + r) * 384 + gcol);
            uint4 u;
            u.x = f2tf32(v.x); u.y = f2tf32(v.y); u.z = f2tf32(v.z); u.w = f2tf32(v.w);
            *(uint4*)&Bs[r * BLD + j0] = u;
        }
        __syncthreads();
#pragma unroll
        for (int ks = 0; ks < 2; ks++) {
            int kk = ks * 8;
            uint32_t afr[2][4];
#pragma unroll
            for (int mt = 0; mt < 2; mt++) {
                int rr = wrow + mt * 16;
                afr[mt][0] = As[(rr + g) * ALD + kk + t4];
                afr[mt][1] = As[(rr + g + 8) * ALD + kk + t4];
                afr[mt][2] = As[(rr + g) * ALD + kk + t4 + 4];
                afr[mt][3] = As[(rr + g + 8) * ALD + kk + t4 + 4];
            }
#pragma unroll
            for (int nt = 0; nt < 6; nt++) {
                int j = ((nt >> 1) << 5) + wn * 16 + ((nt & 1) << 3) + g;
                uint32_t b0 = Bs[(kk + t4) * BLD + j];
                uint32_t b1 = Bs[(kk + t4 + 4) * BLD + j];
#pragma unroll
                for (int mt = 0; mt < 2; mt++)
                    mma_tf32(ah[mt][nt], afr[mt], b0, b1);
            }
        }
        __syncthreads();
    }

    // ======== GRU epilogue (all in registers) ========
#pragma unroll
    for (int mt = 0; mt < 2; mt++) {
#pragma unroll
        for (int p = 0; p < 2; p++) {
            int cb = cslab + wn * 16 + p * 8 + 2 * t4;
            float bir0 = b_ih[cb],       bir1 = b_ih[cb + 1];
            float bhr0 = b_hh[cb],       bhr1 = b_hh[cb + 1];
            float biz0 = b_ih[128 + cb], biz1 = b_ih[129 + cb];
            float bhz0 = b_hh[128 + cb], bhz1 = b_hh[129 + cb];
            float bin0 = b_ih[256 + cb], bin1 = b_ih[257 + cb];
            float bhn0 = b_hh[256 + cb], bhn1 = b_hh[257 + cb];
#pragma unroll
            for (int half = 0; half < 2; half++) {
                int row = bm + wrow + mt * 16 + g + half * 8;
                if (row >= N_AG) continue;
                int q = half * 2;
                float2 hp = *(const float2*)(hprev + (size_t)row * 128 + cb);
                float r0 = sigmoidf(ai[mt][p][q]     + ah[mt][p][q]     + bir0 + bhr0);
                float r1 = sigmoidf(ai[mt][p][q + 1] + ah[mt][p][q + 1] + bir1 + bhr1);
                float z0 = sigmoidf(ai[mt][2 + p][q]     + ah[mt][2 + p][q]     + biz0 + bhz0);
                float z1 = sigmoidf(ai[mt][2 + p][q + 1] + ah[mt][2 + p][q + 1] + biz1 + bhz1);
                float n0 = tanhf(ai[mt][4 + p][q]     + bin0 + r0 * (ah[mt][4 + p][q]     + bhn0));
                float n1 = tanhf(ai[mt][4 + p][q + 1] + bin1 + r1 * (ah[mt][4 + p][q + 1] + bhn1));
                float h0 = (1.f - z0) * n0 + z0 * hp.x;
                float h1 = (1.f - z1) * n1 + z1 * hp.y;
                *(float2*)(hout + (size_t)row * 128 + cb) = make_float2(h0, h1);
                if (write_zz)
                    *(float2*)(out + N_AG * OUTD + (size_t)row * 128 + cb) = make_float2(h0, h1);
            }
        }
    }
}

// ---------------- output projection ----------------
__global__ void k_out(const float* __restrict__ ow, const float* __restrict__ ob,
                      float* __restrict__ out) {
    int gid = blockIdx.x * blockDim.x + threadIdx.x;
    int n = gid >> 5;
    int lane = threadIdx.x & 31;
    if (n >= N_AG) return;
    float p[5] = {0.f, 0.f, 0.f, 0.f, 0.f};
#pragma unroll
    for (int q = 0; q < 4; q++) {
        int d = lane + 32 * q;
        float hv = g_h[n * 128 + d];
#pragma unroll
        for (int o = 0; o < 5; o++) p[o] += hv * ow[d * 5 + o];
    }
#pragma unroll
    for (int o = 0; o < 5; o++) p[o] = warp_sum(p[o]);
    if (lane == 0) {
#pragma unroll
        for (int o = 0; o < 5; o++) out[n * 5 + o] = p[o] + ob[o];
    }
}

// ---------------- launch ----------------
extern "C" void kernel_launch(void* const* d_in, const int* in_sizes, int n_in,
                              void* d_out, int out_size) {
    const float* feat_gt    = (const float*)d_in[0];
    const float* feat_agent = (const float*)d_in[1];
    const float* z          = (const float*)d_in[2];
    const int*   gt_src     = (const int*)d_in[3];
    const int*   gt_dst     = (const int*)d_in[4];
    const int*   cm_src     = (const int*)d_in[5];
    const int*   cm_dst     = (const int*)d_in[6];
    const float* w1_src     = (const float*)d_in[7];
    const float* w1_dst     = (const float*)d_in[8];
    const float* a1_l       = (const float*)d_in[9];
    const float* a1_r       = (const float*)d_in[10];
    const float* b1         = (const float*)d_in[11];
    const float* w2_src     = (const float*)d_in[12];
    const float* w2_dst     = (const float*)d_in[13];
    const float* a2_l       = (const float*)d_in[14];
    const float* a2_r       = (const float*)d_in[15];
    const float* b2         = (const float*)d_in[16];
    const float* enc_w1     = (const float*)d_in[17];
    const float* enc_b1     = (const float*)d_in[18];
    const float* enc_w2     = (const float*)d_in[19];
    const float* enc_b2     = (const float*)d_in[20];
    const float* gru_w_ih   = (const float*)d_in[21];
    const float* gru_w_hh   = (const float*)d_in[22];
    const float* gru_b_ih   = (const float*)d_in[23];
    const float* gru_b_hh   = (const float*)d_in[24];
    const float* out_w      = (const float*)d_in[25];
    const float* out_b      = (const float*)d_in[26];
    float* out = (float*)d_out;

    float *p_h, *p_h2, *p_hidden, *p_m;
    cudaGetSymbolAddress((void**)&p_h, g_h);
    cudaGetSymbolAddress((void**)&p_h2, g_h2);
    cudaGetSymbolAddress((void**)&p_hidden, g_hidden);
    cudaGetSymbolAddress((void**)&p_m, g_m);

    int write_zz = (out_size >= N_AG * OUTD + N_AG * COMM) ? 1 : 0;

    // front-end: init + CSR build + src projection + merged GAT
    k_init<<<192, 256>>>(w1_src, w1_dst, a1_l, a1_r, w2_src, w2_dst, a2_l, a2_r);
    k_hist<<<625, 256>>>(gt_dst, cm_dst);
    k_scan<<<2, 1024>>>();
    k_scatter<<<625, 256>>>(gt_src, gt_dst, cm_src, cm_dst);
    k_srcmma<<<dim3(4, (N_GT + 63) / 64), 256>>>(feat_gt);
    k_gat<<<(N_AG * 32 + 255) / 256, 256>>>(feat_agent, b1, b2);

    const int MB = (N_AG + 127) / 128;
    dim3 ge1(1, MB), ge2(1, MB), ggru(4, MB);

    // comm step 0 (h = g_h, hprev = z) -> writes g_h2
    k_mma<128, 1><<<ge1, 256>>>(p_h, enc_w1, enc_b1, p_hidden, N_AG, 128, 128);
    k_mma<64, 1><<<ge2, 256>>>(p_hidden, enc_w2, enc_b2, p_m, N_AG, 64, 128);
    k_yagg<<<(N_AG * 32 + 255) / 256, 256>>>();
    k_gruf<<<ggru, 256>>>(p_h, z, gru_w_ih, gru_w_hh, gru_b_ih, gru_b_hh, p_h2, out, 0);

    // comm step 1 (h = hprev = g_h2) -> writes g_h (+ zz)
    k_mma<128, 1><<<ge1, 256>>>(p_h2, enc_w1, enc_b1, p_hidden, N_AG, 128, 128);
    k_mma<64, 1><<<ge2, 256>>>(p_hidden, enc_w2, enc_b2, p_m, N_AG, 64, 128);
    k_yagg<<<(N_AG * 32 + 255) / 256, 256>>>();
    k_gruf<<<ggru, 256>>>(p_h2, p_h2, gru_w_ih, gru_w_hh, gru_b_ih, gru_b_hh, p_h, out, write_zz);

    k_out<<<(N_AG * 32 + 255) / 256, 256>>>(out_w, out_b, out);
}

// round 10
// speedup vs baseline: 1.7627x; 1.7627x over previous
#include <cuda_runtime.h>
#include <math.h>
#include <stdint.h>

// ---------------- problem constants ----------------
#define N_GT   100000
#define N_AG   20000
#define E_GT   640000
#define E_COMM 320000
#define E_GT_PAD (E_GT + 31 * N_AG)   // 1,260,000 upper bound after per-row pad
#define D_GT   32
#define D_AG   64
#define VIS    64
#define COMM   128
#define MSG    64
#define OUTD   5
#define LRELU  0.2f

// ---------------- scratch (device globals; no runtime alloc) ----------------
// fsall row layout (stride 256 floats = 1KB): [0:64) fs1, [64:192) fs2, [192:196) el1, [196:200) el2
// row N_GT is a sentinel: fs = 0, el = -100 (dummy edges).
__device__ float g_fsall[(N_GT + 1) * 256];
__device__ float g_bsrc[32 * 256];
__device__ float g_h[N_AG * COMM];
__device__ float g_hidden[N_AG * 128];
__device__ float g_m[N_AG * MSG];
__device__ float g_xcat[N_AG * 192];         // [h | y]
__device__ float g_gi[N_AG * 384];
__device__ float g_gh[N_AG * 384];
__device__ int   g_gt_rowptr[N_AG + 1];      // PADDED offsets (multiples of 32 per row)
__device__ int   g_cm_rowptr[N_AG + 1];
__device__ int   g_gt_cursor[N_AG];
__device__ int   g_cm_cursor[N_AG];
__device__ int   g_gt_srcs[E_GT_PAD];
__device__ int   g_cm_srcs[E_COMM];
__device__ float g_wa1r[64 * 4];
__device__ float g_wa2r[128 * 4];

__device__ __forceinline__ float leaky(float x) { return x >= 0.f ? x : LRELU * x; }
__device__ __forceinline__ float sigmoidf(float x) { return 1.f / (1.f + __expf(-x)); }
__device__ __forceinline__ float warp_sum(float p) {
#pragma unroll
    for (int o = 16; o > 0; o >>= 1) p += __shfl_xor_sync(0xffffffffu, p, o);
    return p;
}
__device__ __forceinline__ uint32_t f2tf32(float x) {
    uint32_t r;
    asm("cvt.rna.tf32.f32 %0, %1;" : "=r"(r) : "f"(x));
    return r;
}
__device__ __forceinline__ void mma_tf32(float* c, const uint32_t* a, uint32_t b0, uint32_t b1) {
    asm volatile(
        "mma.sync.aligned.m16n8k8.row.col.f32.tf32.tf32.f32 "
        "{%0,%1,%2,%3},{%4,%5,%6,%7},{%8,%9},{%0,%1,%2,%3};"
        : "+f"(c[0]), "+f"(c[1]), "+f"(c[2]), "+f"(c[3])
        : "r"(a[0]), "r"(a[1]), "r"(a[2]), "r"(a[3]), "r"(b0), "r"(b1));
}

// ---------------- init: fold attn, pack bsrc, zero rowptrs, sentinel row, fill pad srcs ----------------
#define OFF_W1R  8192
#define OFF_W2R  8448
#define OFF_GT   8960
#define OFF_CM   (OFF_GT + N_AG + 1)
#define OFF_DUM  (OFF_CM + N_AG + 1)
#define OFF_FILL (OFF_DUM + 256)
#define INIT_TOT (OFF_FILL + E_GT_PAD)

__global__ void k_init(const float* __restrict__ w1s, const float* __restrict__ w1d,
                       const float* __restrict__ a1l, const float* __restrict__ a1r,
                       const float* __restrict__ w2s, const float* __restrict__ w2d,
                       const float* __restrict__ a2l, const float* __restrict__ a2r) {
    int i = blockIdx.x * blockDim.x + threadIdx.x;
    if (i >= INIT_TOT) return;
    if (i < 8192) {
        int k = i >> 8, c = i & 255;
        float v = 0.f;
        if (c < 64)       v = w1s[k * 64 + c];
        else if (c < 192) v = w2s[k * 128 + (c - 64)];
        else if (c < 196) {
            int h = c - 192; float s = 0.f;
            for (int d = 0; d < 16; d++) s += w1s[k * 64 + h * 16 + d] * a1l[h * 16 + d];
            v = s;
        } else if (c < 200) {
            int h = c - 196; float s = 0.f;
            for (int d = 0; d < 32; d++) s += w2s[k * 128 + h * 32 + d] * a2l[h * 32 + d];
            v = s;
        }
        g_bsrc[i] = v;
    } else if (i < OFF_W2R) {
        int u = i - OFF_W1R; int k = u >> 2, h = u & 3; float s = 0.f;
        for (int d = 0; d < 16; d++) s += w1d[k * 64 + h * 16 + d] * a1r[h * 16 + d];
        g_wa1r[u] = s;
    } else if (i < OFF_GT) {
        int u = i - OFF_W2R; int k = u >> 2, h = u & 3; float s = 0.f;
        for (int d = 0; d < 32; d++) s += w2d[k * 128 + h * 32 + d] * a2r[h * 32 + d];
        g_wa2r[u] = s;
    } else if (i < OFF_CM) {
        g_gt_rowptr[i - OFF_GT] = 0;
    } else if (i < OFF_DUM) {
        g_cm_rowptr[i - OFF_CM] = 0;
    } else if (i < OFF_FILL) {
        int c = i - OFF_DUM;   // sentinel fsall row
        g_fsall[(size_t)N_GT * 256 + c] = (c >= 192 && c < 200) ? -100.f : 0.f;
    } else {
        g_gt_srcs[i - OFF_FILL] = N_GT;   // pad edges -> sentinel row
    }
}

// ---------------- CSR build ----------------
__global__ void k_hist(const int* __restrict__ gtd, const int* __restrict__ cmd) {
    int i = blockIdx.x * blockDim.x + threadIdx.x;
    if (i < E_GT / 4) {
        int4 d = ((const int4*)gtd)[i];
        atomicAdd(&g_gt_rowptr[d.x + 1], 1);
        atomicAdd(&g_gt_rowptr[d.y + 1], 1);
        atomicAdd(&g_gt_rowptr[d.z + 1], 1);
        atomicAdd(&g_gt_rowptr[d.w + 1], 1);
    }
    if (i < E_COMM / 4) {
        int4 d = ((const int4*)cmd)[i];
        atomicAdd(&g_cm_rowptr[d.x + 1], 1);
        atomicAdd(&g_cm_rowptr[d.y + 1], 1);
        atomicAdd(&g_cm_rowptr[d.z + 1], 1);
        atomicAdd(&g_cm_rowptr[d.w + 1], 1);
    }
}

// scan; block 0 (gt) pads each row count to a multiple of 32. Also inits cursor = row start.
__global__ void k_scan() {
    __shared__ int wsum[32];
    int* a   = (blockIdx.x == 0) ? g_gt_rowptr : g_cm_rowptr;
    int* cur = (blockIdx.x == 0) ? g_gt_cursor : g_cm_cursor;
    const bool pad = (blockIdx.x == 0);
    const int n = N_AG;
    const int PER = 20;
    int t = threadIdx.x, lane = t & 31, wid = t >> 5;
    int base = 1 + t * PER;
    int loc[PER]; int s = 0;
#pragma unroll
    for (int j = 0; j < PER; j++) {
        int idx = base + j;
        int v = (idx <= n) ? a[idx] : 0;
        if (pad) v = (v + 31) & ~31;
        s += v; loc[j] = s;
    }
    int sc = s;
#pragma unroll
    for (int o = 1; o < 32; o <<= 1) {
        int v = __shfl_up_sync(0xffffffffu, sc, o);
        if (lane >= o) sc += v;
    }
    if (lane == 31) wsum[wid] = sc;
    __syncthreads();
    if (wid == 0) {
        int v = wsum[lane];
#pragma unroll
        for (int o = 1; o < 32; o <<= 1) {
            int u = __shfl_up_sync(0xffffffffu, v, o);
            if (lane >= o) v += u;
        }
        wsum[lane] = v;
    }
    __syncthreads();
    int pre = (sc - s) + (wid > 0 ? wsum[wid - 1] : 0);
#pragma unroll
    for (int j = 0; j < PER; j++) {
        int idx = base + j;
        if (idx <= n) {
            int val = loc[j] + pre;
            a[idx] = val;
            if (idx < n) cur[idx] = val;
        }
    }
    if (t == 0) cur[0] = 0;
}

__global__ void k_scatter(const int* __restrict__ gts, const int* __restrict__ gtd,
                          const int* __restrict__ cms, const int* __restrict__ cmd) {
    int i = blockIdx.x * blockDim.x + threadIdx.x;
    if (i < E_GT / 4) {
        int4 s = ((const int4*)gts)[i];
        int4 d = ((const int4*)gtd)[i];
        g_gt_srcs[atomicAdd(&g_gt_cursor[d.x], 1)] = s.x;
        g_gt_srcs[atomicAdd(&g_gt_cursor[d.y], 1)] = s.y;
        g_gt_srcs[atomicAdd(&g_gt_cursor[d.z], 1)] = s.z;
        g_gt_srcs[atomicAdd(&g_gt_cursor[d.w], 1)] = s.w;
    }
    if (i < E_COMM / 4) {
        int4 s = ((const int4*)cms)[i];
        int4 d = ((const int4*)cmd)[i];
        g_cm_srcs[atomicAdd(&g_cm_cursor[d.x], 1)] = s.x;
        g_cm_srcs[atomicAdd(&g_cm_cursor[d.y], 1)] = s.y;
        g_cm_srcs[atomicAdd(&g_cm_cursor[d.z], 1)] = s.z;
        g_cm_srcs[atomicAdd(&g_cm_cursor[d.w], 1)] = s.w;
    }
}

// ---------------- src projection GEMM (split-tf32, fp32-class accuracy) ----------------
__global__ void __launch_bounds__(256) k_srcmma(const float* __restrict__ feat) {
    constexpr int ALD = 36, BLD = 72;
    __shared__ uint32_t Ah[64 * ALD], Al[64 * ALD];
    __shared__ uint32_t Bh[32 * BLD], Bl[32 * BLD];
    int tid = threadIdx.x, lane = tid & 31, warp = tid >> 5;
    int g = lane >> 2, t4 = lane & 3;
    int wrow = (warp >> 1) * 16, wcol = (warp & 1) * 32;
    int bm = blockIdx.y * 64, bn = blockIdx.x * 64;

    float acc[4][4];
#pragma unroll
    for (int nt = 0; nt < 4; nt++)
#pragma unroll
        for (int q = 0; q < 4; q++) acc[nt][q] = 0.f;

#pragma unroll
    for (int it = 0; it < 2; it++) {
        int r = it * 32 + (tid >> 3);
        int c = (tid & 7) * 4;
        int gr = bm + r;
        float4 v = make_float4(0.f, 0.f, 0.f, 0.f);
        if (gr < N_GT) v = *(const float4*)(feat + (size_t)gr * 32 + c);
        uint32_t hx = f2tf32(v.x), hy = f2tf32(v.y), hz = f2tf32(v.z), hw = f2tf32(v.w);
        *(uint4*)&Ah[r * ALD + c] = make_uint4(hx, hy, hz, hw);
        *(uint4*)&Al[r * ALD + c] = make_uint4(f2tf32(v.x - __uint_as_float(hx)),
                                               f2tf32(v.y - __uint_as_float(hy)),
                                               f2tf32(v.z - __uint_as_float(hz)),
                                               f2tf32(v.w - __uint_as_float(hw)));
    }
#pragma unroll
    for (int it = 0; it < 2; it++) {
        int r = it * 16 + (tid >> 4);
        int c = (tid & 15) * 4;
        float4 v = *(const float4*)(g_bsrc + r * 256 + bn + c);
        uint32_t hx = f2tf32(v.x), hy = f2tf32(v.y), hz = f2tf32(v.z), hw = f2tf32(v.w);
        *(uint4*)&Bh[r * BLD + c] = make_uint4(hx, hy, hz, hw);
        *(uint4*)&Bl[r * BLD + c] = make_uint4(f2tf32(v.x - __uint_as_float(hx)),
                                               f2tf32(v.y - __uint_as_float(hy)),
                                               f2tf32(v.z - __uint_as_float(hz)),
                                               f2tf32(v.w - __uint_as_float(hw)));
    }
    __syncthreads();

#pragma unroll
    for (int ks = 0; ks < 4; ks++) {
        int kk = ks * 8;
        uint32_t ah[4], al[4];
        ah[0] = Ah[(wrow + g) * ALD + kk + t4];
        ah[1] = Ah[(wrow + g + 8) * ALD + kk + t4];
        ah[2] = Ah[(wrow + g) * ALD + kk + t4 + 4];
        ah[3] = Ah[(wrow + g + 8) * ALD + kk + t4 + 4];
        al[0] = Al[(wrow + g) * ALD + kk + t4];
        al[1] = Al[(wrow + g + 8) * ALD + kk + t4];
        al[2] = Al[(wrow + g) * ALD + kk + t4 + 4];
        al[3] = Al[(wrow + g + 8) * ALD + kk + t4 + 4];
#pragma unroll
        for (int nt = 0; nt < 4; nt++) {
            int n0 = wcol + nt * 8;
            uint32_t bh0 = Bh[(kk + t4) * BLD + n0 + g];
            uint32_t bh1 = Bh[(kk + t4 + 4) * BLD + n0 + g];
            uint32_t bl0 = Bl[(kk + t4) * BLD + n0 + g];
            uint32_t bl1 = Bl[(kk + t4 + 4) * BLD + n0 + g];
            mma_tf32(acc[nt], ah, bh0, bh1);
            mma_tf32(acc[nt], ah, bl0, bl1);
            mma_tf32(acc[nt], al, bh0, bh1);
        }
    }

#pragma unroll
    for (int nt = 0; nt < 4; nt++) {
        int rr = bm + wrow + g;
        int cc = bn + wcol + nt * 8 + 2 * t4;
        if (cc < 200) {
            if (rr < N_GT)
                *(float2*)(g_fsall + (size_t)rr * 256 + cc) = make_float2(acc[nt][0], acc[nt][1]);
            if (rr + 8 < N_GT)
                *(float2*)(g_fsall + (size_t)(rr + 8) * 256 + cc) = make_float2(acc[nt][2], acc[nt][3]);
        }
    }
}

// ---------------- merged GAT: padded rows -> fully unrolled 32-edge chunks ----------------
__global__ void k_gat(const float* __restrict__ fa_, const float* __restrict__ b1,
                      const float* __restrict__ b2) {
    int gid = blockIdx.x * blockDim.x + threadIdx.x;
    int n = gid >> 5;
    int lane = threadIdx.x & 31;
    if (n >= N_AG) return;
    float fa0 = fa_[n * 64 + lane], fa1 = fa_[n * 64 + lane + 32];
    bool hi = (lane >= 16);
    int beg = g_gt_rowptr[n], end = g_gt_rowptr[n + 1];   // padded, multiple of 32

    // ---- layer 1 ----
    float er0 = warp_sum(fa0 * g_wa1r[lane * 4 + 0] + fa1 * g_wa1r[(lane + 32) * 4 + 0]);
    float er1 = warp_sum(fa0 * g_wa1r[lane * 4 + 1] + fa1 * g_wa1r[(lane + 32) * 4 + 1]);
    float er2 = warp_sum(fa0 * g_wa1r[lane * 4 + 2] + fa1 * g_wa1r[(lane + 32) * 4 + 2]);
    float er3 = warp_sum(fa0 * g_wa1r[lane * 4 + 3] + fa1 * g_wa1r[(lane + 32) * 4 + 3]);
    float acc0 = 0.f, acc1 = 0.f, d0 = 0.f, d1 = 0.f, d2 = 0.f, d3 = 0.f;
    for (int base = beg; base < end; base += 32) {
        int s = g_gt_srcs[base + lane];
        float4 e = *(const float4*)(g_fsall + (size_t)s * 256 + 192);
        float p0 = __expf(leaky(e.x + er0));
        float p1 = __expf(leaky(e.y + er1));
        float p2 = __expf(leaky(e.z + er2));
        float p3 = __expf(leaky(e.w + er3));
        d0 += p0; d1 += p1; d2 += p2; d3 += p3;
#pragma unroll
        for (int j = 0; j < 32; j++) {
            int sj   = __shfl_sync(0xffffffffu, s, j);
            float q0 = __shfl_sync(0xffffffffu, p0, j);
            float q1 = __shfl_sync(0xffffffffu, p1, j);
            float q2 = __shfl_sync(0xffffffffu, p2, j);
            float q3 = __shfl_sync(0xffffffffu, p3, j);
            const float* fr = g_fsall + (size_t)sj * 256;
            acc0 += fr[lane] * (hi ? q1 : q0);
            acc1 += fr[lane + 32] * (hi ? q3 : q2);
        }
    }
    d0 = warp_sum(d0); d1 = warp_sum(d1); d2 = warp_sum(d2); d3 = warp_sum(d3);
    float dlo = hi ? d1 : d0;
    float dhi = hi ? d3 : d2;
    float hv0 = fmaxf((dlo > 0.f ? acc0 / dlo : 0.f) + fa0 + b1[lane], 0.f);
    float hv1 = fmaxf((dhi > 0.f ? acc1 / dhi : 0.f) + fa1 + b1[lane + 32], 0.f);

    // ---- layer 2 ----
    float f0 = warp_sum(hv0 * g_wa2r[lane * 4 + 0] + hv1 * g_wa2r[(lane + 32) * 4 + 0] +
                        fa0 * g_wa2r[(lane + 64) * 4 + 0] + fa1 * g_wa2r[(lane + 96) * 4 + 0]);
    float f1 = warp_sum(hv0 * g_wa2r[lane * 4 + 1] + hv1 * g_wa2r[(lane + 32) * 4 + 1] +
                        fa0 * g_wa2r[(lane + 64) * 4 + 1] + fa1 * g_wa2r[(lane + 96) * 4 + 1]);
    float f2 = warp_sum(hv0 * g_wa2r[lane * 4 + 2] + hv1 * g_wa2r[(lane + 32) * 4 + 2] +
                        fa0 * g_wa2r[(lane + 64) * 4 + 2] + fa1 * g_wa2r[(lane + 96) * 4 + 2]);
    float f3 = warp_sum(hv0 * g_wa2r[lane * 4 + 3] + hv1 * g_wa2r[(lane + 32) * 4 + 3] +
                        fa0 * g_wa2r[(lane + 64) * 4 + 3] + fa1 * g_wa2r[(lane + 96) * 4 + 3]);
    float A0 = 0.f, A1 = 0.f, A2 = 0.f, A3 = 0.f;
    float e0 = 0.f, e1 = 0.f, e2 = 0.f, e3 = 0.f;
    for (int base = beg; base < end; base += 32) {
        int s = g_gt_srcs[base + lane];
        float4 e = *(const float4*)(g_fsall + (size_t)s * 256 + 196);
        float p0 = __expf(leaky(e.x + f0));
        float p1 = __expf(leaky(e.y + f1));
        float p2 = __expf(leaky(e.z + f2));
        float p3 = __expf(leaky(e.w + f3));
        e0 += p0; e1 += p1; e2 += p2; e3 += p3;
#pragma unroll
        for (int j = 0; j < 32; j++) {
            int sj   = __shfl_sync(0xffffffffu, s, j);
            float q0 = __shfl_sync(0xffffffffu, p0, j);
            float q1 = __shfl_sync(0xffffffffu, p1, j);
            float q2 = __shfl_sync(0xffffffffu, p2, j);
            float q3 = __shfl_sync(0xffffffffu, p3, j);
            const float* fr = g_fsall + (size_t)sj * 256 + 64;
            A0 += fr[lane] * q0;
            A1 += fr[lane + 32] * q1;
            A2 += fr[lane + 64] * q2;
            A3 += fr[lane + 96] * q3;
        }
    }
    e0 = warp_sum(e0); e1 = warp_sum(e1); e2 = warp_sum(e2); e3 = warp_sum(e3);
    float r0 = e0 > 0.f ? A0 / e0 : 0.f;
    float r1 = e1 > 0.f ? A1 / e1 : 0.f;
    float r2 = e2 > 0.f ? A2 / e2 : 0.f;
    float r3 = e3 > 0.f ? A3 / e3 : 0.f;
    r0 = fmaxf(r0 + hv0 + b2[lane], 0.f);
    r1 = fmaxf(r1 + hv1 + b2[lane + 32], 0.f);
    r2 = fmaxf(r2 + fa0 + b2[lane + 64], 0.f);
    r3 = fmaxf(r3 + fa1 + b2[lane + 96], 0.f);
    g_h[n * 128 + lane] = r0;         g_xcat[n * 192 + lane] = r0;
    g_h[n * 128 + lane + 32] = r1;    g_xcat[n * 192 + lane + 32] = r1;
    g_h[n * 128 + lane + 64] = r2;    g_xcat[n * 192 + lane + 64] = r2;
    g_h[n * 128 + lane + 96] = r3;    g_xcat[n * 192 + lane + 96] = r3;
}

// ---------------- TF32 tensor-core GEMM (dense layers) ----------------
template <int BN, int RELU>
__global__ void __launch_bounds__(256)
k_mma(const float* __restrict__ A, const float* __restrict__ B,
      const float* __restrict__ bias, float* __restrict__ C,
      int M, int N, int K) {
    constexpr int WN  = BN / 64;
    constexpr int WM  = 8 / WN;
    constexpr int WTM = 128 / WM;
    constexpr int MT  = WTM / 16;
    constexpr int ALD = 36;
    constexpr int BLD = BN + 8;

    __shared__ uint32_t As[128 * ALD];
    __shared__ uint32_t Bs[32 * BLD];

    const int tid  = threadIdx.x;
    const int lane = tid & 31;
    const int warp = tid >> 5;
    const int g    = lane >> 2;
    const int t4   = lane & 3;
    const int wm   = warp / WN;
    const int wn   = warp % WN;
    const int wrow = wm * WTM;
    const int wcol = wn * 64;
    const int bm   = blockIdx.y * 128;
    const int bn   = blockIdx.x * BN;

    float acc[MT][8][4];
#pragma unroll
    for (int mt = 0; mt < MT; mt++)
#pragma unroll
        for (int nt = 0; nt < 8; nt++)
#pragma unroll
            for (int q = 0; q < 4; q++) acc[mt][nt][q] = 0.f;

    for (int k0 = 0; k0 < K; k0 += 32) {
#pragma unroll
        for (int it = 0; it < 4; it++) {
            int r = it * 32 + (tid >> 3);
            int c = (tid & 7) * 4;
            int gr = bm + r;
            float4 v = make_float4(0.f, 0.f, 0.f, 0.f);
            if (gr < M) v = *(const float4*)(A + (size_t)gr * K + k0 + c);
            uint4 u;
            u.x = f2tf32(v.x); u.y = f2tf32(v.y); u.z = f2tf32(v.z); u.w = f2tf32(v.w);
            *(uint4*)&As[r * ALD + c] = u;
        }
        if (BN == 128) {
#pragma unroll
            for (int it = 0; it < 4; it++) {
                int r = it * 8 + (tid >> 5);
                int c = (tid & 31) * 4;
                float4 v = *(const float4*)(B + (size_t)(k0 + r) * N + bn + c);
                uint4 u;
                u.x = f2tf32(v.x); u.y = f2tf32(v.y); u.z = f2tf32(v.z); u.w = f2tf32(v.w);
                *(uint4*)&Bs[r * BLD + c] = u;
            }
        } else {
#pragma unroll
            for (int it = 0; it < 2; it++) {
                int r = it * 16 + (tid >> 4);
                int c = (tid & 15) * 4;
                float4 v = *(const float4*)(B + (size_t)(k0 + r) * N + bn + c);
                uint4 u;
                u.x = f2tf32(v.x); u.y = f2tf32(v.y); u.z = f2tf32(v.z); u.w = f2tf32(v.w);
                *(uint4*)&Bs[r * BLD + c] = u;
            }
        }
        __syncthreads();

#pragma unroll
        for (int ks = 0; ks < 4; ks++) {
            int kk = ks * 8;
            uint32_t a[MT][4];
#pragma unroll
            for (int mt = 0; mt < MT; mt++) {
                int r = wrow + mt * 16;
                a[mt][0] = As[(r + g) * ALD + kk + t4];
                a[mt][1] = As[(r + g + 8) * ALD + kk + t4];
                a[mt][2] = As[(r + g) * ALD + kk + t4 + 4];
                a[mt][3] = As[(r + g + 8) * ALD + kk + t4 + 4];
            }
#pragma unroll
            for (int nt = 0; nt < 8; nt++) {
                int n0 = wcol + nt * 8;
                uint32_t b0 = Bs[(kk + t4) * BLD + n0 + g];
                uint32_t b1 = Bs[(kk + t4 + 4) * BLD + n0 + g];
#pragma unroll
                for (int mt = 0; mt < MT; mt++)
                    mma_tf32(acc[mt][nt], a[mt], b0, b1);
            }
        }
        __syncthreads();
    }

#pragma unroll
    for (int mt = 0; mt < MT; mt++) {
#pragma unroll
        for (int nt = 0; nt < 8; nt++) {
            int rr = bm + wrow + mt * 16 + g;
            int cc = bn + wcol + nt * 8 + 2 * t4;
            float bb0 = bias[cc], bb1 = bias[cc + 1];
            if (rr < M) {
                float v0 = acc[mt][nt][0] + bb0;
                float v1 = acc[mt][nt][1] + bb1;
                if (RELU) { v0 = fmaxf(v0, 0.f); v1 = fmaxf(v1, 0.f); }
                *(float2*)(C + (size_t)rr * N + cc) = make_float2(v0, v1);
            }
            if (rr + 8 < M) {
                float v0 = acc[mt][nt][2] + bb0;
                float v1 = acc[mt][nt][3] + bb1;
                if (RELU) { v0 = fmaxf(v0, 0.f); v1 = fmaxf(v1, 0.f); }
                *(float2*)(C + (size_t)(rr + 8) * N + cc) = make_float2(v0, v1);
            }
        }
    }
}

// ---------------- comm mailbox mean -> xcat[:,128:192] ----------------
__global__ void k_yagg() {
    int gid = blockIdx.x * blockDim.x + threadIdx.x;
    int n = gid >> 5;
    int lane = threadIdx.x & 31;
    if (n >= N_AG) return;
    int beg = g_cm_rowptr[n], end = g_cm_rowptr[n + 1];
    float a0 = 0.f, a1 = 0.f;
    int i = beg;
    for (; i + 1 < end; i += 2) {
        int s0 = g_cm_srcs[i], s1 = g_cm_srcs[i + 1];
        a0 += g_m[s0 * 64 + lane] + g_m[s1 * 64 + lane];
        a1 += g_m[s0 * 64 + lane + 32] + g_m[s1 * 64 + lane + 32];
    }
    if (i < end) {
        int s = g_cm_srcs[i];
        a0 += g_m[s * 64 + lane];
        a1 += g_m[s * 64 + lane + 32];
    }
    float inv = 1.f / fmaxf((float)(end - beg), 1.f);
    g_xcat[n * 192 + 128 + lane] = a0 * inv;
    g_xcat[n * 192 + 160 + lane] = a1 * inv;
}

// ---------------- GRU elementwise ----------------
__global__ void k_gru(const float* __restrict__ hprev) {
    int idx = blockIdx.x * blockDim.x + threadIdx.x;
    if (idx >= N_AG * 128) return;
    int n = idx >> 7, c = idx & 127;
    const float* gi = g_gi + n * 384;
    const float* gh = g_gh + n * 384;
    float r  = sigmoidf(gi[c] + gh[c]);
    float zg = sigmoidf(gi[128 + c] + gh[128 + c]);
    float ng = tanhf(gi[256 + c] + r * gh[256 + c]);
    float hp = hprev[n * 128 + c];
    float hv = (1.f - zg) * ng + zg * hp;
    g_h[idx] = hv;
    g_xcat[n * 192 + c] = hv;
}

// ---------------- output ----------------
__global__ void k_out(const float* __restrict__ ow, const float* __restrict__ ob,
                      float* __restrict__ out, int write_zz) {
    int gid = blockIdx.x * blockDim.x + threadIdx.x;
    int n = gid >> 5;
    int lane = threadIdx.x & 31;
    if (n >= N_AG) return;
    float p[5] = {0.f, 0.f, 0.f, 0.f, 0.f};
#pragma unroll
    for (int q = 0; q < 4; q++) {
        int d = lane + 32 * q;
        float hv = g_h[n * 128 + d];
        if (write_zz) out[N_AG * OUTD + n * 128 + d] = hv;
#pragma unroll
        for (int o = 0; o < 5; o++) p[o] += hv * ow[d * 5 + o];
    }
#pragma unroll
    for (int o = 0; o < 5; o++) p[o] = warp_sum(p[o]);
    if (lane == 0) {
#pragma unroll
        for (int o = 0; o < 5; o++) out[n * 5 + o] = p[o] + ob[o];
    }
}

// ---------------- launch ----------------
extern "C" void kernel_launch(void* const* d_in, const int* in_sizes, int n_in,
                              void* d_out, int out_size) {
    const float* feat_gt    = (const float*)d_in[0];
    const float* feat_agent = (const float*)d_in[1];
    const float* z          = (const float*)d_in[2];
    const int*   gt_src     = (const int*)d_in[3];
    const int*   gt_dst     = (const int*)d_in[4];
    const int*   cm_src     = (const int*)d_in[5];
    const int*   cm_dst     = (const int*)d_in[6];
    const float* w1_src     = (const float*)d_in[7];
    const float* w1_dst     = (const float*)d_in[8];
    const float* a1_l       = (const float*)d_in[9];
    const float* a1_r       = (const float*)d_in[10];
    const float* b1         = (const float*)d_in[11];
    const float* w2_src     = (const float*)d_in[12];
    const float* w2_dst     = (const float*)d_in[13];
    const float* a2_l       = (const float*)d_in[14];
    const float* a2_r       = (const float*)d_in[15];
    const float* b2         = (const float*)d_in[16];
    const float* enc_w1     = (const float*)d_in[17];
    const float* enc_b1     = (const float*)d_in[18];
    const float* enc_w2     = (const float*)d_in[19];
    const float* enc_b2     = (const float*)d_in[20];
    const float* gru_w_ih   = (const float*)d_in[21];
    const float* gru_w_hh   = (const float*)d_in[22];
    const float* gru_b_ih   = (const float*)d_in[23];
    const float* gru_b_hh   = (const float*)d_in[24];
    const float* out_w      = (const float*)d_in[25];
    const float* out_b      = (const float*)d_in[26];
    float* out = (float*)d_out;

    float *p_h, *p_hidden, *p_m, *p_xcat, *p_gi, *p_gh;
    cudaGetSymbolAddress((void**)&p_h, g_h);
    cudaGetSymbolAddress((void**)&p_hidden, g_hidden);
    cudaGetSymbolAddress((void**)&p_m, g_m);
    cudaGetSymbolAddress((void**)&p_xcat, g_xcat);
    cudaGetSymbolAddress((void**)&p_gi, g_gi);
    cudaGetSymbolAddress((void**)&p_gh, g_gh);

    int write_zz = (out_size >= N_AG * OUTD + N_AG * COMM) ? 1 : 0;

    // front-end: init + CSR build (padded gt rows) + src projection + merged GAT
    k_init<<<(INIT_TOT + 255) / 256, 256>>>(w1_src, w1_dst, a1_l, a1_r, w2_src, w2_dst, a2_l, a2_r);
    k_hist<<<625, 256>>>(gt_dst, cm_dst);
    k_scan<<<2, 1024>>>();
    k_scatter<<<625, 256>>>(gt_src, gt_dst, cm_src, cm_dst);
    k_srcmma<<<dim3(4, (N_GT + 63) / 64), 256>>>(feat_gt);
    k_gat<<<(N_AG * 32 + 255) / 256, 256>>>(feat_agent, b1, b2);

    const int MB = (N_AG + 127) / 128;
    dim3 ge1(1, MB), ge2(1, MB), gg(3, MB);
    int gru_grid = (N_AG * 128 + 255) / 256;

    // comm step 0 (hprev = input z)
    k_mma<128, 1><<<ge1, 256>>>(p_h, enc_w1, enc_b1, p_hidden, N_AG, 128, 128);
    k_mma<64, 1><<<ge2, 256>>>(p_hidden, enc_w2, enc_b2, p_m, N_AG, 64, 128);
    k_yagg<<<(N_AG * 32 + 255) / 256, 256>>>();
    k_mma<128, 0><<<gg, 256>>>(p_xcat, gru_w_ih, gru_b_ih, p_gi, N_AG, 384, 192);
    k_mma<128, 0><<<gg, 256>>>(z, gru_w_hh, gru_b_hh, p_gh, N_AG, 384, 128);
    k_gru<<<gru_grid, 256>>>(z);

    // comm step 1 (hprev = h from step 0)
    k_mma<128, 1><<<ge1, 256>>>(p_h, enc_w1, enc_b1, p_hidden, N_AG, 128, 128);
    k_mma<64, 1><<<ge2, 256>>>(p_hidden, enc_w2, enc_b2, p_m, N_AG, 64, 128);
    k_yagg<<<(N_AG * 32 + 255) / 256, 256>>>();
    k_mma<128, 0><<<gg, 256>>>(p_xcat, gru_w_ih, gru_b_ih, p_gi, N_AG, 384, 192);
    k_mma<128, 0><<<gg, 256>>>(p_h, gru_w_hh, gru_b_hh, p_gh, N_AG, 384, 128);
    k_gru<<<gru_grid, 256>>>(p_h);

    k_out<<<(N_AG * 32 + 255) / 256, 256>>>(out_w, out_b, out, write_zz);
}

// round 11
// speedup vs baseline: 1.8358x; 1.0414x over previous
#include <cuda_runtime.h>
#include <math.h>
#include <stdint.h>

// ---------------- problem constants ----------------
#define N_GT   100000
#define N_AG   20000
#define E_GT   640000
#define E_COMM 320000
#define E_GT_PAD (E_GT + 31 * N_AG)      // 1,260,000
#define E_CM_PAD (E_COMM + 31 * N_AG)    //   940,000
#define D_GT   32
#define D_AG   64
#define VIS    64
#define COMM   128
#define MSG    64
#define OUTD   5
#define LRELU  0.2f
#define FSTRIDE 208                      // fsall row stride (floats): [0:64) fs1 | [64:192) fs2 | [192:196) el1 | [196:200) el2

// ---------------- scratch (device globals; no runtime alloc) ----------------
__device__ float g_fsall[(size_t)(N_GT + 1) * FSTRIDE];   // row N_GT = sentinel (fs 0, el -100)
__device__ float g_bsrc[32 * 256];
__device__ float g_h[N_AG * COMM];
__device__ float g_hidden[N_AG * 128];
__device__ float g_m[(N_AG + 1) * MSG];                   // row N_AG = sentinel zeros
__device__ float g_xcat[N_AG * 192];                      // [h | y]
__device__ float g_gi[N_AG * 384];
__device__ float g_gh[N_AG * 384];
__device__ int   g_gt_rowptr[N_AG + 1];                   // padded (multiples of 32)
__device__ int   g_cm_rowptr[N_AG + 1];                   // padded (multiples of 32)
__device__ int   g_gt_cursor[N_AG];                       // after scatter: rowptr + real deg
__device__ int   g_cm_cursor[N_AG];
__device__ int   g_gt_srcs[E_GT_PAD];
__device__ int   g_cm_srcs[E_CM_PAD];
__device__ float g_wa1r[64 * 4];
__device__ float g_wa2r[128 * 4];

__device__ __forceinline__ float leaky(float x) { return x >= 0.f ? x : LRELU * x; }
__device__ __forceinline__ float sigmoidf(float x) { return 1.f / (1.f + __expf(-x)); }
__device__ __forceinline__ float warp_sum(float p) {
#pragma unroll
    for (int o = 16; o > 0; o >>= 1) p += __shfl_xor_sync(0xffffffffu, p, o);
    return p;
}
__device__ __forceinline__ uint32_t f2tf32(float x) {
    uint32_t r;
    asm("cvt.rna.tf32.f32 %0, %1;" : "=r"(r) : "f"(x));
    return r;
}
__device__ __forceinline__ void mma_tf32(float* c, const uint32_t* a, uint32_t b0, uint32_t b1) {
    asm volatile(
        "mma.sync.aligned.m16n8k8.row.col.f32.tf32.tf32.f32 "
        "{%0,%1,%2,%3},{%4,%5,%6,%7},{%8,%9},{%0,%1,%2,%3};"
        : "+f"(c[0]), "+f"(c[1]), "+f"(c[2]), "+f"(c[3])
        : "r"(a[0]), "r"(a[1]), "r"(a[2]), "r"(a[3]), "r"(b0), "r"(b1));
}

// ---------------- init: fold attn, pack bsrc, zero rowptrs, sentinels, pad fills ----------------
#define OFF_W1R  8192
#define OFF_W2R  (OFF_W1R + 256)
#define OFF_GT   (OFF_W2R + 512)
#define OFF_CM   (OFF_GT + N_AG + 1)
#define OFF_DUM  (OFF_CM + N_AG + 1)
#define OFF_MS   (OFF_DUM + FSTRIDE)
#define OFF_FG   (OFF_MS + 64)
#define OFF_FC   (OFF_FG + E_GT_PAD)
#define INIT_TOT (OFF_FC + E_CM_PAD)

__global__ void k_init(const float* __restrict__ w1s, const float* __restrict__ w1d,
                       const float* __restrict__ a1l, const float* __restrict__ a1r,
                       const float* __restrict__ w2s, const float* __restrict__ w2d,
                       const float* __restrict__ a2l, const float* __restrict__ a2r) {
    int i = blockIdx.x * blockDim.x + threadIdx.x;
    if (i >= INIT_TOT) return;
    if (i < 8192) {
        int k = i >> 8, c = i & 255;
        float v = 0.f;
        if (c < 64)       v = w1s[k * 64 + c];
        else if (c < 192) v = w2s[k * 128 + (c - 64)];
        else if (c < 196) {
            int h = c - 192; float s = 0.f;
            for (int d = 0; d < 16; d++) s += w1s[k * 64 + h * 16 + d] * a1l[h * 16 + d];
            v = s;
        } else if (c < 200) {
            int h = c - 196; float s = 0.f;
            for (int d = 0; d < 32; d++) s += w2s[k * 128 + h * 32 + d] * a2l[h * 32 + d];
            v = s;
        }
        g_bsrc[i] = v;
    } else if (i < OFF_W2R) {
        int u = i - OFF_W1R; int k = u >> 2, h = u & 3; float s = 0.f;
        for (int d = 0; d < 16; d++) s += w1d[k * 64 + h * 16 + d] * a1r[h * 16 + d];
        g_wa1r[u] = s;
    } else if (i < OFF_GT) {
        int u = i - OFF_W2R; int k = u >> 2, h = u & 3; float s = 0.f;
        for (int d = 0; d < 32; d++) s += w2d[k * 128 + h * 32 + d] * a2r[h * 32 + d];
        g_wa2r[u] = s;
    } else if (i < OFF_CM) {
        g_gt_rowptr[i - OFF_GT] = 0;
    } else if (i < OFF_DUM) {
        g_cm_rowptr[i - OFF_CM] = 0;
    } else if (i < OFF_MS) {
        int c = i - OFF_DUM;
        g_fsall[(size_t)N_GT * FSTRIDE + c] = (c >= 192 && c < 200) ? -100.f : 0.f;
    } else if (i < OFF_FG) {
        g_m[N_AG * 64 + (i - OFF_MS)] = 0.f;
    } else if (i < OFF_FC) {
        g_gt_srcs[i - OFF_FG] = N_GT;    // pad edges -> sentinel row
    } else {
        g_cm_srcs[i - OFF_FC] = N_AG;    // pad edges -> sentinel row
    }
}

// ---------------- CSR build ----------------
__global__ void k_hist(const int* __restrict__ gtd, const int* __restrict__ cmd) {
    int i = blockIdx.x * blockDim.x + threadIdx.x;
    if (i < E_GT / 4) {
        int4 d = ((const int4*)gtd)[i];
        atomicAdd(&g_gt_rowptr[d.x + 1], 1);
        atomicAdd(&g_gt_rowptr[d.y + 1], 1);
        atomicAdd(&g_gt_rowptr[d.z + 1], 1);
        atomicAdd(&g_gt_rowptr[d.w + 1], 1);
    }
    if (i < E_COMM / 4) {
        int4 d = ((const int4*)cmd)[i];
        atomicAdd(&g_cm_rowptr[d.x + 1], 1);
        atomicAdd(&g_cm_rowptr[d.y + 1], 1);
        atomicAdd(&g_cm_rowptr[d.z + 1], 1);
        atomicAdd(&g_cm_rowptr[d.w + 1], 1);
    }
}

// scan with per-row pad-to-32 (both graphs); inits cursor = row start.
__global__ void k_scan() {
    __shared__ int wsum[32];
    int* a   = (blockIdx.x == 0) ? g_gt_rowptr : g_cm_rowptr;
    int* cur = (blockIdx.x == 0) ? g_gt_cursor : g_cm_cursor;
    const int n = N_AG;
    const int PER = 20;
    int t = threadIdx.x, lane = t & 31, wid = t >> 5;
    int base = 1 + t * PER;
    int loc[PER]; int s = 0;
#pragma unroll
    for (int j = 0; j < PER; j++) {
        int idx = base + j;
        int v = (idx <= n) ? a[idx] : 0;
        v = (v + 31) & ~31;
        s += v; loc[j] = s;
    }
    int sc = s;
#pragma unroll
    for (int o = 1; o < 32; o <<= 1) {
        int v = __shfl_up_sync(0xffffffffu, sc, o);
        if (lane >= o) sc += v;
    }
    if (lane == 31) wsum[wid] = sc;
    __syncthreads();
    if (wid == 0) {
        int v = wsum[lane];
#pragma unroll
        for (int o = 1; o < 32; o <<= 1) {
            int u = __shfl_up_sync(0xffffffffu, v, o);
            if (lane >= o) v += u;
        }
        wsum[lane] = v;
    }
    __syncthreads();
    int pre = (sc - s) + (wid > 0 ? wsum[wid - 1] : 0);
#pragma unroll
    for (int j = 0; j < PER; j++) {
        int idx = base + j;
        if (idx <= n) {
            int val = loc[j] + pre;
            a[idx] = val;
            if (idx < n) cur[idx] = val;
        }
    }
    if (t == 0) cur[0] = 0;
}

__global__ void k_scatter(const int* __restrict__ gts, const int* __restrict__ gtd,
                          const int* __restrict__ cms, const int* __restrict__ cmd) {
    int i = blockIdx.x * blockDim.x + threadIdx.x;
    if (i < E_GT / 4) {
        int4 s = ((const int4*)gts)[i];
        int4 d = ((const int4*)gtd)[i];
        g_gt_srcs[atomicAdd(&g_gt_cursor[d.x], 1)] = s.x;
        g_gt_srcs[atomicAdd(&g_gt_cursor[d.y], 1)] = s.y;
        g_gt_srcs[atomicAdd(&g_gt_cursor[d.z], 1)] = s.z;
        g_gt_srcs[atomicAdd(&g_gt_cursor[d.w], 1)] = s.w;
    }
    if (i < E_COMM / 4) {
        int4 s = ((const int4*)cms)[i];
        int4 d = ((const int4*)cmd)[i];
        g_cm_srcs[atomicAdd(&g_cm_cursor[d.x], 1)] = s.x;
        g_cm_srcs[atomicAdd(&g_cm_cursor[d.y], 1)] = s.y;
        g_cm_srcs[atomicAdd(&g_cm_cursor[d.z], 1)] = s.z;
        g_cm_srcs[atomicAdd(&g_cm_cursor[d.w], 1)] = s.w;
    }
}

// ---------------- src projection GEMM (split-tf32, fp32-class accuracy) ----------------
__global__ void __launch_bounds__(256) k_srcmma(const float* __restrict__ feat) {
    constexpr int ALD = 36, BLD = 72;
    __shared__ uint32_t Ah[64 * ALD], Al[64 * ALD];
    __shared__ uint32_t Bh[32 * BLD], Bl[32 * BLD];
    int tid = threadIdx.x, lane = tid & 31, warp = tid >> 5;
    int g = lane >> 2, t4 = lane & 3;
    int wrow = (warp >> 1) * 16, wcol = (warp & 1) * 32;
    int bm = blockIdx.y * 64, bn = blockIdx.x * 64;

    float acc[4][4];
#pragma unroll
    for (int nt = 0; nt < 4; nt++)
#pragma unroll
        for (int q = 0; q < 4; q++) acc[nt][q] = 0.f;

#pragma unroll
    for (int it = 0; it < 2; it++) {
        int r = it * 32 + (tid >> 3);
        int c = (tid & 7) * 4;
        int gr = bm + r;
        float4 v = make_float4(0.f, 0.f, 0.f, 0.f);
        if (gr < N_GT) v = *(const float4*)(feat + (size_t)gr * 32 + c);
        uint32_t hx = f2tf32(v.x), hy = f2tf32(v.y), hz = f2tf32(v.z), hw = f2tf32(v.w);
        *(uint4*)&Ah[r * ALD + c] = make_uint4(hx, hy, hz, hw);
        *(uint4*)&Al[r * ALD + c] = make_uint4(f2tf32(v.x - __uint_as_float(hx)),
                                               f2tf32(v.y - __uint_as_float(hy)),
                                               f2tf32(v.z - __uint_as_float(hz)),
                                               f2tf32(v.w - __uint_as_float(hw)));
    }
#pragma unroll
    for (int it = 0; it < 2; it++) {
        int r = it * 16 + (tid >> 4);
        int c = (tid & 15) * 4;
        float4 v = *(const float4*)(g_bsrc + r * 256 + bn + c);
        uint32_t hx = f2tf32(v.x), hy = f2tf32(v.y), hz = f2tf32(v.z), hw = f2tf32(v.w);
        *(uint4*)&Bh[r * BLD + c] = make_uint4(hx, hy, hz, hw);
        *(uint4*)&Bl[r * BLD + c] = make_uint4(f2tf32(v.x - __uint_as_float(hx)),
                                               f2tf32(v.y - __uint_as_float(hy)),
                                               f2tf32(v.z - __uint_as_float(hz)),
                                               f2tf32(v.w - __uint_as_float(hw)));
    }
    __syncthreads();

#pragma unroll
    for (int ks = 0; ks < 4; ks++) {
        int kk = ks * 8;
        uint32_t ah[4], al[4];
        ah[0] = Ah[(wrow + g) * ALD + kk + t4];
        ah[1] = Ah[(wrow + g + 8) * ALD + kk + t4];
        ah[2] = Ah[(wrow + g) * ALD + kk + t4 + 4];
        ah[3] = Ah[(wrow + g + 8) * ALD + kk + t4 + 4];
        al[0] = Al[(wrow + g) * ALD + kk + t4];
        al[1] = Al[(wrow + g + 8) * ALD + kk + t4];
        al[2] = Al[(wrow + g) * ALD + kk + t4 + 4];
        al[3] = Al[(wrow + g + 8) * ALD + kk + t4 + 4];
#pragma unroll
        for (int nt = 0; nt < 4; nt++) {
            int n0 = wcol + nt * 8;
            uint32_t bh0 = Bh[(kk + t4) * BLD + n0 + g];
            uint32_t bh1 = Bh[(kk + t4 + 4) * BLD + n0 + g];
            uint32_t bl0 = Bl[(kk + t4) * BLD + n0 + g];
            uint32_t bl1 = Bl[(kk + t4 + 4) * BLD + n0 + g];
            mma_tf32(acc[nt], ah, bh0, bh1);
            mma_tf32(acc[nt], ah, bl0, bl1);
            mma_tf32(acc[nt], al, bh0, bh1);
        }
    }

#pragma unroll
    for (int nt = 0; nt < 4; nt++) {
        int rr = bm + wrow + g;
        int cc = bn + wcol + nt * 8 + 2 * t4;
        if (cc < 200) {
            if (rr < N_GT)
                *(float2*)(g_fsall + (size_t)rr * FSTRIDE + cc) = make_float2(acc[nt][0], acc[nt][1]);
            if (rr + 8 < N_GT)
                *(float2*)(g_fsall + (size_t)(rr + 8) * FSTRIDE + cc) = make_float2(acc[nt][2], acc[nt][3]);
        }
    }
}

// ---------------- merged GAT: dim-vectorized loads, smem weight broadcast, el2/srcs cached ----------------
__global__ void __launch_bounds__(256) k_gat(const float* __restrict__ fa_,
                                             const float* __restrict__ b1,
                                             const float* __restrict__ b2) {
    __shared__ float s_w[8][128];      // per-chunk softmax weights, [4*edge + head]
    __shared__ float s_el2[8][256];    // cached el2 for first 2 chunks
    __shared__ int   s_src[8][64];     // cached srcs for first 2 chunks
    __shared__ float s_hv[8][64];      // layer1 output
    __shared__ float s_fa[8][64];      // staged feat_agent

    int gid = blockIdx.x * blockDim.x + threadIdx.x;
    int n = gid >> 5;
    int lane = threadIdx.x & 31;
    int wi = threadIdx.x >> 5;
    if (n >= N_AG) return;
    const int h = lane >> 3;           // head for this lane's dims (both layers)

    float2 fav = *(const float2*)(fa_ + (size_t)n * 64 + 2 * lane);
    *(float2*)&s_fa[wi][2 * lane] = fav;
    __syncwarp();

    int beg = g_gt_rowptr[n], end = g_gt_rowptr[n + 1];   // padded, multiple of 32

    // ---- layer 1: er (attention-dst term) ----
    float4 w0 = *(const float4*)(g_wa1r + (2 * lane) * 4);
    float4 w1 = *(const float4*)(g_wa1r + (2 * lane + 1) * 4);
    float er0 = warp_sum(fav.x * w0.x + fav.y * w1.x);
    float er1 = warp_sum(fav.x * w0.y + fav.y * w1.y);
    float er2 = warp_sum(fav.x * w0.z + fav.y * w1.z);
    float er3 = warp_sum(fav.x * w0.w + fav.y * w1.w);

    float accx = 0.f, accy = 0.f;
    float d0 = 0.f, d1 = 0.f, d2 = 0.f, d3 = 0.f;
    int c = 0;
    for (int base = beg; base < end; base += 32, c++) {
        int s = g_gt_srcs[base + lane];
        const float* rowp = g_fsall + (size_t)s * FSTRIDE;
        float4 e1 = *(const float4*)(rowp + 192);
        float4 e2 = *(const float4*)(rowp + 196);
        float p0 = __expf(leaky(e1.x + er0));
        float p1 = __expf(leaky(e1.y + er1));
        float p2 = __expf(leaky(e1.z + er2));
        float p3 = __expf(leaky(e1.w + er3));
        d0 += p0; d1 += p1; d2 += p2; d3 += p3;
        *(float4*)&s_w[wi][4 * lane] = make_float4(p0, p1, p2, p3);
        if (c < 2) {
            s_src[wi][(c << 5) + lane] = s;
            *(float4*)&s_el2[wi][((c << 5) + lane) * 4] = e2;
        }
        __syncwarp();
#pragma unroll
        for (int j = 0; j < 32; j++) {
            int sj = __shfl_sync(0xffffffffu, s, j);
            float q = s_w[wi][4 * j + h];
            float2 fr = *(const float2*)(g_fsall + (size_t)sj * FSTRIDE + 2 * lane);
            accx += fr.x * q;
            accy += fr.y * q;
        }
        __syncwarp();
    }
    d0 = warp_sum(d0); d1 = warp_sum(d1); d2 = warp_sum(d2); d3 = warp_sum(d3);
    float dd = (h == 0) ? d0 : (h == 1) ? d1 : (h == 2) ? d2 : d3;
    float2 bb1 = *(const float2*)(b1 + 2 * lane);
    float hv0 = fmaxf((dd > 0.f ? accx / dd : 0.f) + fav.x + bb1.x, 0.f);
    float hv1 = fmaxf((dd > 0.f ? accy / dd : 0.f) + fav.y + bb1.y, 0.f);
    *(float2*)&s_hv[wi][2 * lane] = make_float2(hv0, hv1);
    __syncwarp();

    // ---- layer 2: f (attention-dst term on [hv | fa]) ----
    float4 u0 = *(const float4*)(g_wa2r + (2 * lane) * 4);
    float4 u1 = *(const float4*)(g_wa2r + (2 * lane + 1) * 4);
    float4 u2 = *(const float4*)(g_wa2r + (64 + 2 * lane) * 4);
    float4 u3 = *(const float4*)(g_wa2r + (64 + 2 * lane + 1) * 4);
    float f0 = warp_sum(hv0 * u0.x + hv1 * u1.x + fav.x * u2.x + fav.y * u3.x);
    float f1 = warp_sum(hv0 * u0.y + hv1 * u1.y + fav.x * u2.y + fav.y * u3.y);
    float f2 = warp_sum(hv0 * u0.z + hv1 * u1.z + fav.x * u2.z + fav.y * u3.z);
    float f3 = warp_sum(hv0 * u0.w + hv1 * u1.w + fav.x * u2.w + fav.y * u3.w);

    float4 a2 = make_float4(0.f, 0.f, 0.f, 0.f);
    float e0s = 0.f, e1s = 0.f, e2s = 0.f, e3s = 0.f;
    c = 0;
    for (int base = beg; base < end; base += 32, c++) {
        int s; float4 e2;
        if (c < 2) {
            s = s_src[wi][(c << 5) + lane];
            e2 = *(const float4*)&s_el2[wi][((c << 5) + lane) * 4];
        } else {
            s = g_gt_srcs[base + lane];
            e2 = *(const float4*)(g_fsall + (size_t)s * FSTRIDE + 196);
        }
        float p0 = __expf(leaky(e2.x + f0));
        float p1 = __expf(leaky(e2.y + f1));
        float p2 = __expf(leaky(e2.z + f2));
        float p3 = __expf(leaky(e2.w + f3));
        e0s += p0; e1s += p1; e2s += p2; e3s += p3;
        *(float4*)&s_w[wi][4 * lane] = make_float4(p0, p1, p2, p3);
        __syncwarp();
#pragma unroll
        for (int j = 0; j < 32; j++) {
            int sj = __shfl_sync(0xffffffffu, s, j);
            float q = s_w[wi][4 * j + h];
            float4 fr = *(const float4*)(g_fsall + (size_t)sj * FSTRIDE + 64 + 4 * lane);
            a2.x += fr.x * q; a2.y += fr.y * q;
            a2.z += fr.z * q; a2.w += fr.w * q;
        }
        __syncwarp();
    }
    e0s = warp_sum(e0s); e1s = warp_sum(e1s); e2s = warp_sum(e2s); e3s = warp_sum(e3s);
    float ee = (h == 0) ? e0s : (h == 1) ? e1s : (h == 2) ? e2s : e3s;
    float inv = ee > 0.f ? 1.f / ee : 0.f;

    float4 resid = (lane < 16) ? *(const float4*)&s_hv[wi][4 * lane]
                               : *(const float4*)&s_fa[wi][4 * lane - 64];
    float4 bb2 = *(const float4*)(b2 + 4 * lane);
    float4 r;
    r.x = fmaxf(a2.x * inv + resid.x + bb2.x, 0.f);
    r.y = fmaxf(a2.y * inv + resid.y + bb2.y, 0.f);
    r.z = fmaxf(a2.z * inv + resid.z + bb2.z, 0.f);
    r.w = fmaxf(a2.w * inv + resid.w + bb2.w, 0.f);
    *(float4*)(g_h + (size_t)n * 128 + 4 * lane) = r;
    *(float4*)(g_xcat + (size_t)n * 192 + 4 * lane) = r;
}

// ---------------- TF32 tensor-core GEMM (dense layers) ----------------
template <int BN, int RELU>
__global__ void __launch_bounds__(256)
k_mma(const float* __restrict__ A, const float* __restrict__ B,
      const float* __restrict__ bias, float* __restrict__ C,
      int M, int N, int K) {
    constexpr int WN  = BN / 64;
    constexpr int WM  = 8 / WN;
    constexpr int WTM = 128 / WM;
    constexpr int MT  = WTM / 16;
    constexpr int ALD = 36;
    constexpr int BLD = BN + 8;

    __shared__ uint32_t As[128 * ALD];
    __shared__ uint32_t Bs[32 * BLD];

    const int tid  = threadIdx.x;
    const int lane = tid & 31;
    const int warp = tid >> 5;
    const int g    = lane >> 2;
    const int t4   = lane & 3;
    const int wm   = warp / WN;
    const int wn   = warp % WN;
    const int wrow = wm * WTM;
    const int wcol = wn * 64;
    const int bm   = blockIdx.y * 128;
    const int bn   = blockIdx.x * BN;

    float acc[MT][8][4];
#pragma unroll
    for (int mt = 0; mt < MT; mt++)
#pragma unroll
        for (int nt = 0; nt < 8; nt++)
#pragma unroll
            for (int q = 0; q < 4; q++) acc[mt][nt][q] = 0.f;

    for (int k0 = 0; k0 < K; k0 += 32) {
#pragma unroll
        for (int it = 0; it < 4; it++) {
            int r = it * 32 + (tid >> 3);
            int c = (tid & 7) * 4;
            int gr = bm + r;
            float4 v = make_float4(0.f, 0.f, 0.f, 0.f);
            if (gr < M) v = *(const float4*)(A + (size_t)gr * K + k0 + c);
            uint4 u;
            u.x = f2tf32(v.x); u.y = f2tf32(v.y); u.z = f2tf32(v.z); u.w = f2tf32(v.w);
            *(uint4*)&As[r * ALD + c] = u;
        }
        if (BN == 128) {
#pragma unroll
            for (int it = 0; it < 4; it++) {
                int r = it * 8 + (tid >> 5);
                int c = (tid & 31) * 4;
                float4 v = *(const float4*)(B + (size_t)(k0 + r) * N + bn + c);
                uint4 u;
                u.x = f2tf32(v.x); u.y = f2tf32(v.y); u.z = f2tf32(v.z); u.w = f2tf32(v.w);
                *(uint4*)&Bs[r * BLD + c] = u;
            }
        } else {
#pragma unroll
            for (int it = 0; it < 2; it++) {
                int r = it * 16 + (tid >> 4);
                int c = (tid & 15) * 4;
                float4 v = *(const float4*)(B + (size_t)(k0 + r) * N + bn + c);
                uint4 u;
                u.x = f2tf32(v.x); u.y = f2tf32(v.y); u.z = f2tf32(v.z); u.w = f2tf32(v.w);
                *(uint4*)&Bs[r * BLD + c] = u;
            }
        }
        __syncthreads();

#pragma unroll
        for (int ks = 0; ks < 4; ks++) {
            int kk = ks * 8;
            uint32_t a[MT][4];
#pragma unroll
            for (int mt = 0; mt < MT; mt++) {
                int r = wrow + mt * 16;
                a[mt][0] = As[(r + g) * ALD + kk + t4];
                a[mt][1] = As[(r + g + 8) * ALD + kk + t4];
                a[mt][2] = As[(r + g) * ALD + kk + t4 + 4];
                a[mt][3] = As[(r + g + 8) * ALD + kk + t4 + 4];
            }
#pragma unroll
            for (int nt = 0; nt < 8; nt++) {
                int n0 = wcol + nt * 8;
                uint32_t b0 = Bs[(kk + t4) * BLD + n0 + g];
                uint32_t b1 = Bs[(kk + t4 + 4) * BLD + n0 + g];
#pragma unroll
                for (int mt = 0; mt < MT; mt++)
                    mma_tf32(acc[mt][nt], a[mt], b0, b1);
            }
        }
        __syncthreads();
    }

#pragma unroll
    for (int mt = 0; mt < MT; mt++) {
#pragma unroll
        for (int nt = 0; nt < 8; nt++) {
            int rr = bm + wrow + mt * 16 + g;
            int cc = bn + wcol + nt * 8 + 2 * t4;
            float bb0 = bias[cc], bb1 = bias[cc + 1];
            if (rr < M) {
                float v0 = acc[mt][nt][0] + bb0;
                float v1 = acc[mt][nt][1] + bb1;
                if (RELU) { v0 = fmaxf(v0, 0.f); v1 = fmaxf(v1, 0.f); }
                *(float2*)(C + (size_t)rr * N + cc) = make_float2(v0, v1);
            }
            if (rr + 8 < M) {
                float v0 = acc[mt][nt][2] + bb0;
                float v1 = acc[mt][nt][3] + bb1;
                if (RELU) { v0 = fmaxf(v0, 0.f); v1 = fmaxf(v1, 0.f); }
                *(float2*)(C + (size_t)(rr + 8) * N + cc) = make_float2(v0, v1);
            }
        }
    }
}

// ---------------- comm mailbox mean -> xcat[:,128:192] (padded rows) ----------------
__global__ void k_yagg() {
    int gid = blockIdx.x * blockDim.x + threadIdx.x;
    int n = gid >> 5;
    int lane = threadIdx.x & 31;
    if (n >= N_AG) return;
    int beg = g_cm_rowptr[n], end = g_cm_rowptr[n + 1];   // padded
    int realdeg = g_cm_cursor[n] - beg;
    float ax = 0.f, ay = 0.f;
    for (int base = beg; base < end; base += 32) {
        int s = g_cm_srcs[base + lane];
#pragma unroll
        for (int j = 0; j < 32; j++) {
            int sj = __shfl_sync(0xffffffffu, s, j);
            float2 m = *(const float2*)(g_m + (size_t)sj * 64 + 2 * lane);
            ax += m.x; ay += m.y;
        }
    }
    float inv = 1.f / fmaxf((float)realdeg, 1.f);
    *(float2*)(g_xcat + (size_t)n * 192 + 128 + 2 * lane) = make_float2(ax * inv, ay * inv);
}

// ---------------- GRU elementwise ----------------
__global__ void k_gru(const float* __restrict__ hprev) {
    int idx = blockIdx.x * blockDim.x + threadIdx.x;
    if (idx >= N_AG * 128) return;
    int n = idx >> 7, c = idx & 127;
    const float* gi = g_gi + n * 384;
    const float* gh = g_gh + n * 384;
    float r  = sigmoidf(gi[c] + gh[c]);
    float zg = sigmoidf(gi[128 + c] + gh[128 + c]);
    float ng = tanhf(gi[256 + c] + r * gh[256 + c]);
    float hp = hprev[n * 128 + c];
    float hv = (1.f - zg) * ng + zg * hp;
    g_h[idx] = hv;
    g_xcat[n * 192 + c] = hv;
}

// ---------------- output ----------------
__global__ void k_out(const float* __restrict__ ow, const float* __restrict__ ob,
                      float* __restrict__ out, int write_zz) {
    int gid = blockIdx.x * blockDim.x + threadIdx.x;
    int n = gid >> 5;
    int lane = threadIdx.x & 31;
    if (n >= N_AG) return;
    float p[5] = {0.f, 0.f, 0.f, 0.f, 0.f};
#pragma unroll
    for (int q = 0; q < 4; q++) {
        int d = lane + 32 * q;
        float hv = g_h[n * 128 + d];
        if (write_zz) out[N_AG * OUTD + n * 128 + d] = hv;
#pragma unroll
        for (int o = 0; o < 5; o++) p[o] += hv * ow[d * 5 + o];
    }
#pragma unroll
    for (int o = 0; o < 5; o++) p[o] = warp_sum(p[o]);
    if (lane == 0) {
#pragma unroll
        for (int o = 0; o < 5; o++) out[n * 5 + o] = p[o] + ob[o];
    }
}

// ---------------- launch ----------------
extern "C" void kernel_launch(void* const* d_in, const int* in_sizes, int n_in,
                              void* d_out, int out_size) {
    const float* feat_gt    = (const float*)d_in[0];
    const float* feat_agent = (const float*)d_in[1];
    const float* z          = (const float*)d_in[2];
    const int*   gt_src     = (const int*)d_in[3];
    const int*   gt_dst     = (const int*)d_in[4];
    const int*   cm_src     = (const int*)d_in[5];
    const int*   cm_dst     = (const int*)d_in[6];
    const float* w1_src     = (const float*)d_in[7];
    const float* w1_dst     = (const float*)d_in[8];
    const float* a1_l       = (const float*)d_in[9];
    const float* a1_r       = (const float*)d_in[10];
    const float* b1         = (const float*)d_in[11];
    const float* w2_src     = (const float*)d_in[12];
    const float* w2_dst     = (const float*)d_in[13];
    const float* a2_l       = (const float*)d_in[14];
    const float* a2_r       = (const float*)d_in[15];
    const float* b2         = (const float*)d_in[16];
    const float* enc_w1     = (const float*)d_in[17];
    const float* enc_b1     = (const float*)d_in[18];
    const float* enc_w2     = (const float*)d_in[19];
    const float* enc_b2     = (const float*)d_in[20];
    const float* gru_w_ih   = (const float*)d_in[21];
    const float* gru_w_hh   = (const float*)d_in[22];
    const float* gru_b_ih   = (const float*)d_in[23];
    const float* gru_b_hh   = (const float*)d_in[24];
    const float* out_w      = (const float*)d_in[25];
    const float* out_b      = (const float*)d_in[26];
    float* out = (float*)d_out;

    float *p_h, *p_hidden, *p_m, *p_xcat, *p_gi, *p_gh;
    cudaGetSymbolAddress((void**)&p_h, g_h);
    cudaGetSymbolAddress((void**)&p_hidden, g_hidden);
    cudaGetSymbolAddress((void**)&p_m, g_m);
    cudaGetSymbolAddress((void**)&p_xcat, g_xcat);
    cudaGetSymbolAddress((void**)&p_gi, g_gi);
    cudaGetSymbolAddress((void**)&p_gh, g_gh);

    int write_zz = (out_size >= N_AG * OUTD + N_AG * COMM) ? 1 : 0;

    // front-end (srcmma placed 4th so ncu's fixed profile slot lands on it)
    k_init<<<(INIT_TOT + 255) / 256, 256>>>(w1_src, w1_dst, a1_l, a1_r, w2_src, w2_dst, a2_l, a2_r);
    k_hist<<<625, 256>>>(gt_dst, cm_dst);
    k_scan<<<2, 1024>>>();
    k_srcmma<<<dim3(4, (N_GT + 63) / 64), 256>>>(feat_gt);
    k_scatter<<<625, 256>>>(gt_src, gt_dst, cm_src, cm_dst);
    k_gat<<<(N_AG * 32 + 255) / 256, 256>>>(feat_agent, b1, b2);

    const int MB = (N_AG + 127) / 128;
    dim3 ge1(1, MB), ge2(1, MB), gg(3, MB);
    int gru_grid = (N_AG * 128 + 255) / 256;

    // comm step 0 (hprev = input z)
    k_mma<128, 1><<<ge1, 256>>>(p_h, enc_w1, enc_b1, p_hidden, N_AG, 128, 128);
    k_mma<64, 1><<<ge2, 256>>>(p_hidden, enc_w2, enc_b2, p_m, N_AG, 64, 128);
    k_yagg<<<(N_AG * 32 + 255) / 256, 256>>>();
    k_mma<128, 0><<<gg, 256>>>(p_xcat, gru_w_ih, gru_b_ih, p_gi, N_AG, 384, 192);
    k_mma<128, 0><<<gg, 256>>>(z, gru_w_hh, gru_b_hh, p_gh, N_AG, 384, 128);
    k_gru<<<gru_grid, 256>>>(z);

    // comm step 1 (hprev = h from step 0)
    k_mma<128, 1><<<ge1, 256>>>(p_h, enc_w1, enc_b1, p_hidden, N_AG, 128, 128);
    k_mma<64, 1><<<ge2, 256>>>(p_hidden, enc_w2, enc_b2, p_m, N_AG, 64, 128);
    k_yagg<<<(N_AG * 32 + 255) / 256, 256>>>();
    k_mma<128, 0><<<gg, 256>>>(p_xcat, gru_w_ih, gru_b_ih, p_gi, N_AG, 384, 192);
    k_mma<128, 0><<<gg, 256>>>(p_h, gru_w_hh, gru_b_hh, p_gh, N_AG, 384, 128);
    k_gru<<<gru_grid, 256>>>(p_h);

    k_out<<<(N_AG * 32 + 255) / 256, 256>>>(out_w, out_b, out, write_zz);
}

// round 14
// speedup vs baseline: 1.9339x; 1.0535x over previous
#include <cuda_runtime.h>
#include <math.h>
#include <stdint.h>

// ---------------- problem constants ----------------
#define N_GT   100000
#define N_AG   20000
#define E_GT   640000
#define E_COMM 320000
#define E_GT_PAD (E_GT + 31 * N_AG)      // 1,260,000
#define E_CM_PAD (E_COMM + 31 * N_AG)    //   940,000
#define D_GT   32
#define D_AG   64
#define VIS    64
#define COMM   128
#define MSG    64
#define OUTD   5
#define LRELU  0.2f
#define FSTRIDE 208                      // fsall row stride (floats): [0:64) fs1 | [64:192) fs2 | [192:196) el1 | [196:200) el2

// ---------------- scratch (device globals; no runtime alloc) ----------------
__device__ float g_fsall[(size_t)(N_GT + 1) * FSTRIDE];   // row N_GT = sentinel (fs 0, el -100)
__device__ float g_bsrc[32 * 256];
__device__ float g_h[N_AG * COMM];
__device__ float g_hidden[N_AG * 128];
__device__ float g_m[(N_AG + 1) * MSG];                   // row N_AG = sentinel zeros
__device__ float g_xcat[N_AG * 192];                      // [h | y]
__device__ float g_gi[N_AG * 384];
__device__ float g_gh[N_AG * 384];
__device__ int   g_gt_rowptr[N_AG + 1];                   // padded (multiples of 32)
__device__ int   g_cm_rowptr[N_AG + 1];                   // padded (multiples of 32)
__device__ int   g_gt_cursor[N_AG];                       // after scatter: rowptr + real deg
__device__ int   g_cm_cursor[N_AG];
__device__ int   g_gt_srcs[E_GT_PAD];
__device__ int   g_cm_srcs[E_CM_PAD];
__device__ float g_wa1r[64 * 4];
__device__ float g_wa2r[128 * 4];

__device__ __forceinline__ float leaky(float x) { return x >= 0.f ? x : LRELU * x; }
__device__ __forceinline__ float sigmoidf(float x) { return 1.f / (1.f + __expf(-x)); }
__device__ __forceinline__ float warp_sum(float p) {
#pragma unroll
    for (int o = 16; o > 0; o >>= 1) p += __shfl_xor_sync(0xffffffffu, p, o);
    return p;
}
__device__ __forceinline__ uint32_t f2tf32(float x) {
    uint32_t r;
    asm("cvt.rna.tf32.f32 %0, %1;" : "=r"(r) : "f"(x));
    return r;
}
__device__ __forceinline__ void mma_tf32(float* c, const uint32_t* a, uint32_t b0, uint32_t b1) {
    asm volatile(
        "mma.sync.aligned.m16n8k8.row.col.f32.tf32.tf32.f32 "
        "{%0,%1,%2,%3},{%4,%5,%6,%7},{%8,%9},{%0,%1,%2,%3};"
        : "+f"(c[0]), "+f"(c[1]), "+f"(c[2]), "+f"(c[3])
        : "r"(a[0]), "r"(a[1]), "r"(a[2]), "r"(a[3]), "r"(b0), "r"(b1));
}

// ---------------- init: fold attn, pack bsrc, zero rowptrs, sentinels, pad fills ----------------
#define OFF_W1R  8192
#define OFF_W2R  (OFF_W1R + 256)
#define OFF_GT   (OFF_W2R + 512)
#define OFF_CM   (OFF_GT + N_AG + 1)
#define OFF_DUM  (OFF_CM + N_AG + 1)
#define OFF_MS   (OFF_DUM + FSTRIDE)
#define OFF_FG   (OFF_MS + 64)
#define OFF_FC   (OFF_FG + E_GT_PAD)
#define INIT_TOT (OFF_FC + E_CM_PAD)

__global__ void k_init(const float* __restrict__ w1s, const float* __restrict__ w1d,
                       const float* __restrict__ a1l, const float* __restrict__ a1r,
                       const float* __restrict__ w2s, const float* __restrict__ w2d,
                       const float* __restrict__ a2l, const float* __restrict__ a2r) {
    int i = blockIdx.x * blockDim.x + threadIdx.x;
    if (i >= INIT_TOT) return;
    if (i < 8192) {
        int k = i >> 8, c = i & 255;
        float v = 0.f;
        if (c < 64)       v = w1s[k * 64 + c];
        else if (c < 192) v = w2s[k * 128 + (c - 64)];
        else if (c < 196) {
            int h = c - 192; float s = 0.f;
            for (int d = 0; d < 16; d++) s += w1s[k * 64 + h * 16 + d] * a1l[h * 16 + d];
            v = s;
        } else if (c < 200) {
            int h = c - 196; float s = 0.f;
            for (int d = 0; d < 32; d++) s += w2s[k * 128 + h * 32 + d] * a2l[h * 32 + d];
            v = s;
        }
        g_bsrc[i] = v;
    } else if (i < OFF_W2R) {
        int u = i - OFF_W1R; int k = u >> 2, h = u & 3; float s = 0.f;
        for (int d = 0; d < 16; d++) s += w1d[k * 64 + h * 16 + d] * a1r[h * 16 + d];
        g_wa1r[u] = s;
    } else if (i < OFF_GT) {
        int u = i - OFF_W2R; int k = u >> 2, h = u & 3; float s = 0.f;
        for (int d = 0; d < 32; d++) s += w2d[k * 128 + h * 32 + d] * a2r[h * 32 + d];
        g_wa2r[u] = s;
    } else if (i < OFF_CM) {
        g_gt_rowptr[i - OFF_GT] = 0;
    } else if (i < OFF_DUM) {
        g_cm_rowptr[i - OFF_CM] = 0;
    } else if (i < OFF_MS) {
        int c = i - OFF_DUM;
        g_fsall[(size_t)N_GT * FSTRIDE + c] = (c >= 192 && c < 200) ? -100.f : 0.f;
    } else if (i < OFF_FG) {
        g_m[N_AG * 64 + (i - OFF_MS)] = 0.f;
    } else if (i < OFF_FC) {
        g_gt_srcs[i - OFF_FG] = N_GT;    // pad edges -> sentinel row
    } else {
        g_cm_srcs[i - OFF_FC] = N_AG;    // pad edges -> sentinel row
    }
}

// ---------------- CSR build ----------------
__global__ void k_hist(const int* __restrict__ gtd, const int* __restrict__ cmd) {
    int i = blockIdx.x * blockDim.x + threadIdx.x;
    if (i < E_GT / 4) {
        int4 d = ((const int4*)gtd)[i];
        atomicAdd(&g_gt_rowptr[d.x + 1], 1);
        atomicAdd(&g_gt_rowptr[d.y + 1], 1);
        atomicAdd(&g_gt_rowptr[d.z + 1], 1);
        atomicAdd(&g_gt_rowptr[d.w + 1], 1);
    }
    if (i < E_COMM / 4) {
        int4 d = ((const int4*)cmd)[i];
        atomicAdd(&g_cm_rowptr[d.x + 1], 1);
        atomicAdd(&g_cm_rowptr[d.y + 1], 1);
        atomicAdd(&g_cm_rowptr[d.z + 1], 1);
        atomicAdd(&g_cm_rowptr[d.w + 1], 1);
    }
}

// scan with per-row pad-to-32 (both graphs); inits cursor = row start.
__global__ void k_scan() {
    __shared__ int wsum[32];
    int* a   = (blockIdx.x == 0) ? g_gt_rowptr : g_cm_rowptr;
    int* cur = (blockIdx.x == 0) ? g_gt_cursor : g_cm_cursor;
    const int n = N_AG;
    const int PER = 20;
    int t = threadIdx.x, lane = t & 31, wid = t >> 5;
    int base = 1 + t * PER;
    int loc[PER]; int s = 0;
#pragma unroll
    for (int j = 0; j < PER; j++) {
        int idx = base + j;
        int v = (idx <= n) ? a[idx] : 0;
        v = (v + 31) & ~31;
        s += v; loc[j] = s;
    }
    int sc = s;
#pragma unroll
    for (int o = 1; o < 32; o <<= 1) {
        int v = __shfl_up_sync(0xffffffffu, sc, o);
        if (lane >= o) sc += v;
    }
    if (lane == 31) wsum[wid] = sc;
    __syncthreads();
    if (wid == 0) {
        int v = wsum[lane];
#pragma unroll
        for (int o = 1; o < 32; o <<= 1) {
            int u = __shfl_up_sync(0xffffffffu, v, o);
            if (lane >= o) v += u;
        }
        wsum[lane] = v;
    }
    __syncthreads();
    int pre = (sc - s) + (wid > 0 ? wsum[wid - 1] : 0);
#pragma unroll
    for (int j = 0; j < PER; j++) {
        int idx = base + j;
        if (idx <= n) {
            int val = loc[j] + pre;
            a[idx] = val;
            if (idx < n) cur[idx] = val;
        }
    }
    if (t == 0) cur[0] = 0;
}

__global__ void k_scatter(const int* __restrict__ gts, const int* __restrict__ gtd,
                          const int* __restrict__ cms, const int* __restrict__ cmd) {
    int i = blockIdx.x * blockDim.x + threadIdx.x;
    if (i < E_GT / 4) {
        int4 s = ((const int4*)gts)[i];
        int4 d = ((const int4*)gtd)[i];
        g_gt_srcs[atomicAdd(&g_gt_cursor[d.x], 1)] = s.x;
        g_gt_srcs[atomicAdd(&g_gt_cursor[d.y], 1)] = s.y;
        g_gt_srcs[atomicAdd(&g_gt_cursor[d.z], 1)] = s.z;
        g_gt_srcs[atomicAdd(&g_gt_cursor[d.w], 1)] = s.w;
    }
    if (i < E_COMM / 4) {
        int4 s = ((const int4*)cms)[i];
        int4 d = ((const int4*)cmd)[i];
        g_cm_srcs[atomicAdd(&g_cm_cursor[d.x], 1)] = s.x;
        g_cm_srcs[atomicAdd(&g_cm_cursor[d.y], 1)] = s.y;
        g_cm_srcs[atomicAdd(&g_cm_cursor[d.z], 1)] = s.z;
        g_cm_srcs[atomicAdd(&g_cm_cursor[d.w], 1)] = s.w;
    }
}

// ---------------- src projection GEMM (split-tf32, fp32-class accuracy) ----------------
__global__ void __launch_bounds__(256) k_srcmma(const float* __restrict__ feat) {
    constexpr int ALD = 36, BLD = 72;
    __shared__ uint32_t Ah[64 * ALD], Al[64 * ALD];
    __shared__ uint32_t Bh[32 * BLD], Bl[32 * BLD];
    int tid = threadIdx.x, lane = tid & 31, warp = tid >> 5;
    int g = lane >> 2, t4 = lane & 3;
    int wrow = (warp >> 1) * 16, wcol = (warp & 1) * 32;
    int bm = blockIdx.y * 64, bn = blockIdx.x * 64;

    float acc[4][4];
#pragma unroll
    for (int nt = 0; nt < 4; nt++)
#pragma unroll
        for (int q = 0; q < 4; q++) acc[nt][q] = 0.f;

#pragma unroll
    for (int it = 0; it < 2; it++) {
        int r = it * 32 + (tid >> 3);
        int c = (tid & 7) * 4;
        int gr = bm + r;
        float4 v = make_float4(0.f, 0.f, 0.f, 0.f);
        if (gr < N_GT) v = *(const float4*)(feat + (size_t)gr * 32 + c);
        uint32_t hx = f2tf32(v.x), hy = f2tf32(v.y), hz = f2tf32(v.z), hw = f2tf32(v.w);
        *(uint4*)&Ah[r * ALD + c] = make_uint4(hx, hy, hz, hw);
        *(uint4*)&Al[r * ALD + c] = make_uint4(f2tf32(v.x - __uint_as_float(hx)),
                                               f2tf32(v.y - __uint_as_float(hy)),
                                               f2tf32(v.z - __uint_as_float(hz)),
                                               f2tf32(v.w - __uint_as_float(hw)));
    }
#pragma unroll
    for (int it = 0; it < 2; it++) {
        int r = it * 16 + (tid >> 4);
        int c = (tid & 15) * 4;
        float4 v = *(const float4*)(g_bsrc + r * 256 + bn + c);
        uint32_t hx = f2tf32(v.x), hy = f2tf32(v.y), hz = f2tf32(v.z), hw = f2tf32(v.w);
        *(uint4*)&Bh[r * BLD + c] = make_uint4(hx, hy, hz, hw);
        *(uint4*)&Bl[r * BLD + c] = make_uint4(f2tf32(v.x - __uint_as_float(hx)),
                                               f2tf32(v.y - __uint_as_float(hy)),
                                               f2tf32(v.z - __uint_as_float(hz)),
                                               f2tf32(v.w - __uint_as_float(hw)));
    }
    __syncthreads();

#pragma unroll
    for (int ks = 0; ks < 4; ks++) {
        int kk = ks * 8;
        uint32_t ah[4], al[4];
        ah[0] = Ah[(wrow + g) * ALD + kk + t4];
        ah[1] = Ah[(wrow + g + 8) * ALD + kk + t4];
        ah[2] = Ah[(wrow + g) * ALD + kk + t4 + 4];
        ah[3] = Ah[(wrow + g + 8) * ALD + kk + t4 + 4];
        al[0] = Al[(wrow + g) * ALD + kk + t4];
        al[1] = Al[(wrow + g + 8) * ALD + kk + t4];
        al[2] = Al[(wrow + g) * ALD + kk + t4 + 4];
        al[3] = Al[(wrow + g + 8) * ALD + kk + t4 + 4];
#pragma unroll
        for (int nt = 0; nt < 4; nt++) {
            int n0 = wcol + nt * 8;
            uint32_t bh0 = Bh[(kk + t4) * BLD + n0 + g];
            uint32_t bh1 = Bh[(kk + t4 + 4) * BLD + n0 + g];
            uint32_t bl0 = Bl[(kk + t4) * BLD + n0 + g];
            uint32_t bl1 = Bl[(kk + t4 + 4) * BLD + n0 + g];
            mma_tf32(acc[nt], ah, bh0, bh1);
            mma_tf32(acc[nt], ah, bl0, bl1);
            mma_tf32(acc[nt], al, bh0, bh1);
        }
    }

#pragma unroll
    for (int nt = 0; nt < 4; nt++) {
        int rr = bm + wrow + g;
        int cc = bn + wcol + nt * 8 + 2 * t4;
        if (cc < 200) {
            if (rr < N_GT)
                *(float2*)(g_fsall + (size_t)rr * FSTRIDE + cc) = make_float2(acc[nt][0], acc[nt][1]);
            if (rr + 8 < N_GT)
                *(float2*)(g_fsall + (size_t)(rr + 8) * FSTRIDE + cc) = make_float2(acc[nt][2], acc[nt][3]);
        }
    }
}

// ---------------- merged GAT: vectorized gathers over REAL edges only ----------------
__global__ void __launch_bounds__(256) k_gat(const float* __restrict__ fa_,
                                             const float* __restrict__ b1,
                                             const float* __restrict__ b2) {
    __shared__ float s_w[8][128];      // per-chunk softmax weights, [4*edge + head]
    __shared__ float s_el2[8][256];    // cached el2 for first 2 chunks
    __shared__ int   s_src[8][64];     // cached srcs for first 2 chunks
    __shared__ float s_hv[8][64];      // layer1 output
    __shared__ float s_fa[8][64];      // staged feat_agent

    int gid = blockIdx.x * blockDim.x + threadIdx.x;
    int n = gid >> 5;
    int lane = threadIdx.x & 31;
    int wi = threadIdx.x >> 5;
    if (n >= N_AG) return;
    const int h = lane >> 3;           // head for this lane's dims (both layers)

    float2 fav = *(const float2*)(fa_ + (size_t)n * 64 + 2 * lane);
    *(float2*)&s_fa[wi][2 * lane] = fav;
    __syncwarp();

    int beg = g_gt_rowptr[n], end = g_gt_rowptr[n + 1];   // padded, multiple of 32
    int realend = g_gt_cursor[n];                         // beg + real degree

    // ---- layer 1: er (attention-dst term) ----
    float4 w0 = *(const float4*)(g_wa1r + (2 * lane) * 4);
    float4 w1 = *(const float4*)(g_wa1r + (2 * lane + 1) * 4);
    float er0 = warp_sum(fav.x * w0.x + fav.y * w1.x);
    float er1 = warp_sum(fav.x * w0.y + fav.y * w1.y);
    float er2 = warp_sum(fav.x * w0.z + fav.y * w1.z);
    float er3 = warp_sum(fav.x * w0.w + fav.y * w1.w);

    float accx = 0.f, accy = 0.f;
    float d0 = 0.f, d1 = 0.f, d2 = 0.f, d3 = 0.f;
    int c = 0;
    for (int base = beg; base < end; base += 32, c++) {
        int s = g_gt_srcs[base + lane];
        const float* rowp = g_fsall + (size_t)s * FSTRIDE;
        float4 e1 = *(const float4*)(rowp + 192);
        float4 e2 = *(const float4*)(rowp + 196);
        float p0 = __expf(leaky(e1.x + er0));
        float p1 = __expf(leaky(e1.y + er1));
        float p2 = __expf(leaky(e1.z + er2));
        float p3 = __expf(leaky(e1.w + er3));
        d0 += p0; d1 += p1; d2 += p2; d3 += p3;
        *(float4*)&s_w[wi][4 * lane] = make_float4(p0, p1, p2, p3);
        if (c < 2) {
            s_src[wi][(c << 5) + lane] = s;
            *(float4*)&s_el2[wi][((c << 5) + lane) * 4] = e2;
        }
        __syncwarp();
        int jcnt = min(32, realend - base);   // gather only REAL edges (pad features are 0)
        for (int j = 0; j < jcnt; j++) {
            int sj = __shfl_sync(0xffffffffu, s, j);
            float q = s_w[wi][4 * j + h];
            float2 fr = *(const float2*)(g_fsall + (size_t)sj * FSTRIDE + 2 * lane);
            accx += fr.x * q;
            accy += fr.y * q;
        }
        __syncwarp();
    }
    d0 = warp_sum(d0); d1 = warp_sum(d1); d2 = warp_sum(d2); d3 = warp_sum(d3);
    float dd = (h == 0) ? d0 : (h == 1) ? d1 : (h == 2) ? d2 : d3;
    float2 bb1 = *(const float2*)(b1 + 2 * lane);
    float hv0 = fmaxf((dd > 0.f ? accx / dd : 0.f) + fav.x + bb1.x, 0.f);
    float hv1 = fmaxf((dd > 0.f ? accy / dd : 0.f) + fav.y + bb1.y, 0.f);
    *(float2*)&s_hv[wi][2 * lane] = make_float2(hv0, hv1);
    __syncwarp();

    // ---- layer 2: f (attention-dst term on [hv | fa]) ----
    float4 u0 = *(const float4*)(g_wa2r + (2 * lane) * 4);
    float4 u1 = *(const float4*)(g_wa2r + (2 * lane + 1) * 4);
    float4 u2 = *(const float4*)(g_wa2r + (64 + 2 * lane) * 4);
    float4 u3 = *(const float4*)(g_wa2r + (64 + 2 * lane + 1) * 4);
    float f0 = warp_sum(hv0 * u0.x + hv1 * u1.x + fav.x * u2.x + fav.y * u3.x);
    float f1 = warp_sum(hv0 * u0.y + hv1 * u1.y + fav.x * u2.y + fav.y * u3.y);
    float f2 = warp_sum(hv0 * u0.z + hv1 * u1.z + fav.x * u2.z + fav.y * u3.z);
    float f3 = warp_sum(hv0 * u0.w + hv1 * u1.w + fav.x * u2.w + fav.y * u3.w);

    float4 a2 = make_float4(0.f, 0.f, 0.f, 0.f);
    float e0s = 0.f, e1s = 0.f, e2s = 0.f, e3s = 0.f;
    c = 0;
    for (int base = beg; base < end; base += 32, c++) {
        int s; float4 e2;
        if (c < 2) {
            s = s_src[wi][(c << 5) + lane];
            e2 = *(const float4*)&s_el2[wi][((c << 5) + lane) * 4];
        } else {
            s = g_gt_srcs[base + lane];
            e2 = *(const float4*)(g_fsall + (size_t)s * FSTRIDE + 196);
        }
        float p0 = __expf(leaky(e2.x + f0));
        float p1 = __expf(leaky(e2.y + f1));
        float p2 = __expf(leaky(e2.z + f2));
        float p3 = __expf(leaky(e2.w + f3));
        e0s += p0; e1s += p1; e2s += p2; e3s += p3;
        *(float4*)&s_w[wi][4 * lane] = make_float4(p0, p1, p2, p3);
        __syncwarp();
        int jcnt = min(32, realend - base);
        for (int j = 0; j < jcnt; j++) {
            int sj = __shfl_sync(0xffffffffu, s, j);
            float q = s_w[wi][4 * j + h];
            float4 fr = *(const float4*)(g_fsall + (size_t)sj * FSTRIDE + 64 + 4 * lane);
            a2.x += fr.x * q; a2.y += fr.y * q;
            a2.z += fr.z * q; a2.w += fr.w * q;
        }
        __syncwarp();
    }
    e0s = warp_sum(e0s); e1s = warp_sum(e1s); e2s = warp_sum(e2s); e3s = warp_sum(e3s);
    float ee = (h == 0) ? e0s : (h == 1) ? e1s : (h == 2) ? e2s : e3s;
    float inv = ee > 0.f ? 1.f / ee : 0.f;

    float4 resid = (lane < 16) ? *(const float4*)&s_hv[wi][4 * lane]
                               : *(const float4*)&s_fa[wi][4 * lane - 64];
    float4 bb2 = *(const float4*)(b2 + 4 * lane);
    float4 r;
    r.x = fmaxf(a2.x * inv + resid.x + bb2.x, 0.f);
    r.y = fmaxf(a2.y * inv + resid.y + bb2.y, 0.f);
    r.z = fmaxf(a2.z * inv + resid.z + bb2.z, 0.f);
    r.w = fmaxf(a2.w * inv + resid.w + bb2.w, 0.f);
    *(float4*)(g_h + (size_t)n * 128 + 4 * lane) = r;
    *(float4*)(g_xcat + (size_t)n * 192 + 4 * lane) = r;
}

// ---------------- TF32 tensor-core GEMM (dense layers; optional dual problem via blockIdx.z) ----------------
template <int BN, int RELU, int DUAL>
__global__ void __launch_bounds__(256)
k_mma(const float* __restrict__ A, const float* __restrict__ B,
      const float* __restrict__ bias, float* __restrict__ C,
      int M, int N, int K,
      const float* A2, const float* B2, const float* bias2, float* C2, int K2) {
    if (DUAL && blockIdx.z == 1) { A = A2; B = B2; bias = bias2; C = C2; K = K2; }
    constexpr int WN  = BN / 64;
    constexpr int WM  = 8 / WN;
    constexpr int WTM = 128 / WM;
    constexpr int MT  = WTM / 16;
    constexpr int ALD = 36;
    constexpr int BLD = BN + 8;

    __shared__ uint32_t As[128 * ALD];
    __shared__ uint32_t Bs[32 * BLD];

    const int tid  = threadIdx.x;
    const int lane = tid & 31;
    const int warp = tid >> 5;
    const int g    = lane >> 2;
    const int t4   = lane & 3;
    const int wm   = warp / WN;
    const int wn   = warp % WN;
    const int wrow = wm * WTM;
    const int wcol = wn * 64;
    const int bm   = blockIdx.y * 128;
    const int bn   = blockIdx.x * BN;

    float acc[MT][8][4];
#pragma unroll
    for (int mt = 0; mt < MT; mt++)
#pragma unroll
        for (int nt = 0; nt < 8; nt++)
#pragma unroll
            for (int q = 0; q < 4; q++) acc[mt][nt][q] = 0.f;

    for (int k0 = 0; k0 < K; k0 += 32) {
#pragma unroll
        for (int it = 0; it < 4; it++) {
            int r = it * 32 + (tid >> 3);
            int c = (tid & 7) * 4;
            int gr = bm + r;
            float4 v = make_float4(0.f, 0.f, 0.f, 0.f);
            if (gr < M) v = *(const float4*)(A + (size_t)gr * K + k0 + c);
            uint4 u;
            u.x = f2tf32(v.x); u.y = f2tf32(v.y); u.z = f2tf32(v.z); u.w = f2tf32(v.w);
            *(uint4*)&As[r * ALD + c] = u;
        }
        if (BN == 128) {
#pragma unroll
            for (int it = 0; it < 4; it++) {
                int r = it * 8 + (tid >> 5);
                int c = (tid & 31) * 4;
                float4 v = *(const float4*)(B + (size_t)(k0 + r) * N + bn + c);
                uint4 u;
                u.x = f2tf32(v.x); u.y = f2tf32(v.y); u.z = f2tf32(v.z); u.w = f2tf32(v.w);
                *(uint4*)&Bs[r * BLD + c] = u;
            }
        } else {
#pragma unroll
            for (int it = 0; it < 2; it++) {
                int r = it * 16 + (tid >> 4);
                int c = (tid & 15) * 4;
                float4 v = *(const float4*)(B + (size_t)(k0 + r) * N + bn + c);
                uint4 u;
                u.x = f2tf32(v.x); u.y = f2tf32(v.y); u.z = f2tf32(v.z); u.w = f2tf32(v.w);
                *(uint4*)&Bs[r * BLD + c] = u;
            }
        }
        __syncthreads();

#pragma unroll
        for (int ks = 0; ks < 4; ks++) {
            int kk = ks * 8;
            uint32_t a[MT][4];
#pragma unroll
            for (int mt = 0; mt < MT; mt++) {
                int r = wrow + mt * 16;
                a[mt][0] = As[(r + g) * ALD + kk + t4];
                a[mt][1] = As[(r + g + 8) * ALD + kk + t4];
                a[mt][2] = As[(r + g) * ALD + kk + t4 + 4];
                a[mt][3] = As[(r + g + 8) * ALD + kk + t4 + 4];
            }
#pragma unroll
            for (int nt = 0; nt < 8; nt++) {
                int n0 = wcol + nt * 8;
                uint32_t b0 = Bs[(kk + t4) * BLD + n0 + g];
                uint32_t b1 = Bs[(kk + t4 + 4) * BLD + n0 + g];
#pragma unroll
                for (int mt = 0; mt < MT; mt++)
                    mma_tf32(acc[mt][nt], a[mt], b0, b1);
            }
        }
        __syncthreads();
    }

#pragma unroll
    for (int mt = 0; mt < MT; mt++) {
#pragma unroll
        for (int nt = 0; nt < 8; nt++) {
            int rr = bm + wrow + mt * 16 + g;
            int cc = bn + wcol + nt * 8 + 2 * t4;
            float bb0 = bias[cc], bb1 = bias[cc + 1];
            if (rr < M) {
                float v0 = acc[mt][nt][0] + bb0;
                float v1 = acc[mt][nt][1] + bb1;
                if (RELU) { v0 = fmaxf(v0, 0.f); v1 = fmaxf(v1, 0.f); }
                *(float2*)(C + (size_t)rr * N + cc) = make_float2(v0, v1);
            }
            if (rr + 8 < M) {
                float v0 = acc[mt][nt][2] + bb0;
                float v1 = acc[mt][nt][3] + bb1;
                if (RELU) { v0 = fmaxf(v0, 0.f); v1 = fmaxf(v1, 0.f); }
                *(float2*)(C + (size_t)(rr + 8) * N + cc) = make_float2(v0, v1);
            }
        }
    }
}

// ---------------- comm mailbox mean -> xcat[:,128:192] (real edges only) ----------------
__global__ void k_yagg() {
    int gid = blockIdx.x * blockDim.x + threadIdx.x;
    int n = gid >> 5;
    int lane = threadIdx.x & 31;
    if (n >= N_AG) return;
    int beg = g_cm_rowptr[n], end = g_cm_rowptr[n + 1];   // padded
    int realend = g_cm_cursor[n];
    float ax = 0.f, ay = 0.f;
    for (int base = beg; base < end; base += 32) {
        int s = g_cm_srcs[base + lane];
        int jcnt = min(32, realend - base);
        for (int j = 0; j < jcnt; j++) {
            int sj = __shfl_sync(0xffffffffu, s, j);
            float2 m = *(const float2*)(g_m + (size_t)sj * 64 + 2 * lane);
            ax += m.x; ay += m.y;
        }
    }
    float inv = 1.f / fmaxf((float)(realend - beg), 1.f);
    *(float2*)(g_xcat + (size_t)n * 192 + 128 + 2 * lane) = make_float2(ax * inv, ay * inv);
}

// ---------------- GRU elementwise ----------------
__global__ void k_gru(const float* __restrict__ hprev) {
    int idx = blockIdx.x * blockDim.x + threadIdx.x;
    if (idx >= N_AG * 128) return;
    int n = idx >> 7, c = idx & 127;
    const float* gi = g_gi + n * 384;
    const float* gh = g_gh + n * 384;
    float r  = sigmoidf(gi[c] + gh[c]);
    float zg = sigmoidf(gi[128 + c] + gh[128 + c]);
    float ng = tanhf(gi[256 + c] + r * gh[256 + c]);
    float hp = hprev[n * 128 + c];
    float hv = (1.f - zg) * ng + zg * hp;
    g_h[idx] = hv;
    g_xcat[n * 192 + c] = hv;
}

// ---------------- output ----------------
__global__ void k_out(const float* __restrict__ ow, const float* __restrict__ ob,
                      float* __restrict__ out, int write_zz) {
    int gid = blockIdx.x * blockDim.x + threadIdx.x;
    int n = gid >> 5;
    int lane = threadIdx.x & 31;
    if (n >= N_AG) return;
    float p[5] = {0.f, 0.f, 0.f, 0.f, 0.f};
#pragma unroll
    for (int q = 0; q < 4; q++) {
        int d = lane + 32 * q;
        float hv = g_h[n * 128 + d];
        if (write_zz) out[N_AG * OUTD + n * 128 + d] = hv;
#pragma unroll
        for (int o = 0; o < 5; o++) p[o] += hv * ow[d * 5 + o];
    }
#pragma unroll
    for (int o = 0; o < 5; o++) p[o] = warp_sum(p[o]);
    if (lane == 0) {
#pragma unroll
        for (int o = 0; o < 5; o++) out[n * 5 + o] = p[o] + ob[o];
    }
}

// ---------------- launch ----------------
extern "C" void kernel_launch(void* const* d_in, const int* in_sizes, int n_in,
                              void* d_out, int out_size) {
    const float* feat_gt    = (const float*)d_in[0];
    const float* feat_agent = (const float*)d_in[1];
    const float* z          = (const float*)d_in[2];
    const int*   gt_src     = (const int*)d_in[3];
    const int*   gt_dst     = (const int*)d_in[4];
    const int*   cm_src     = (const int*)d_in[5];
    const int*   cm_dst     = (const int*)d_in[6];
    const float* w1_src     = (const float*)d_in[7];
    const float* w1_dst     = (const float*)d_in[8];
    const float* a1_l       = (const float*)d_in[9];
    const float* a1_r       = (const float*)d_in[10];
    const float* b1         = (const float*)d_in[11];
    const float* w2_src     = (const float*)d_in[12];
    const float* w2_dst     = (const float*)d_in[13];
    const float* a2_l       = (const float*)d_in[14];
    const float* a2_r       = (const float*)d_in[15];
    const float* b2         = (const float*)d_in[16];
    const float* enc_w1     = (const float*)d_in[17];
    const float* enc_b1     = (const float*)d_in[18];
    const float* enc_w2     = (const float*)d_in[19];
    const float* enc_b2     = (const float*)d_in[20];
    const float* gru_w_ih   = (const float*)d_in[21];
    const float* gru_w_hh   = (const float*)d_in[22];
    const float* gru_b_ih   = (const float*)d_in[23];
    const float* gru_b_hh   = (const float*)d_in[24];
    const float* out_w      = (const float*)d_in[25];
    const float* out_b      = (const float*)d_in[26];
    float* out = (float*)d_out;

    float *p_h, *p_hidden, *p_m, *p_xcat, *p_gi, *p_gh;
    cudaGetSymbolAddress((void**)&p_h, g_h);
    cudaGetSymbolAddress((void**)&p_hidden, g_hidden);
    cudaGetSymbolAddress((void**)&p_m, g_m);
    cudaGetSymbolAddress((void**)&p_xcat, g_xcat);
    cudaGetSymbolAddress((void**)&p_gi, g_gi);
    cudaGetSymbolAddress((void**)&p_gh, g_gh);

    int write_zz = (out_size >= N_AG * OUTD + N_AG * COMM) ? 1 : 0;

    // front-end
    k_init<<<(INIT_TOT + 255) / 256, 256>>>(w1_src, w1_dst, a1_l, a1_r, w2_src, w2_dst, a2_l, a2_r);
    k_hist<<<625, 256>>>(gt_dst, cm_dst);
    k_scan<<<2, 1024>>>();
    k_srcmma<<<dim3(4, (N_GT + 63) / 64), 256>>>(feat_gt);
    k_scatter<<<625, 256>>>(gt_src, gt_dst, cm_src, cm_dst);
    k_gat<<<(N_AG * 32 + 255) / 256, 256>>>(feat_agent, b1, b2);

    const int MB = (N_AG + 127) / 128;
    dim3 ge1(1, MB), ge2(1, MB);
    dim3 ggru(3, MB, 2);
    int gru_grid = (N_AG * 128 + 255) / 256;

    // comm step 0 (hprev = input z)
    k_mma<128, 1, 0><<<ge1, 256>>>(p_h, enc_w1, enc_b1, p_hidden, N_AG, 128, 128,
                                   nullptr, nullptr, nullptr, nullptr, 0);
    k_mma<64, 1, 0><<<ge2, 256>>>(p_hidden, enc_w2, enc_b2, p_m, N_AG, 64, 128,
                                  nullptr, nullptr, nullptr, nullptr, 0);
    k_yagg<<<(N_AG * 32 + 255) / 256, 256>>>();
    k_mma<128, 0, 1><<<ggru, 256>>>(p_xcat, gru_w_ih, gru_b_ih, p_gi, N_AG, 384, 192,
                                    z, gru_w_hh, gru_b_hh, p_gh, 128);
    k_gru<<<gru_grid, 256>>>(z);

    // comm step 1 (hprev = h from step 0)
    k_mma<128, 1, 0><<<ge1, 256>>>(p_h, enc_w1, enc_b1, p_hidden, N_AG, 128, 128,
                                   nullptr, nullptr, nullptr, nullptr, 0);
    k_mma<64, 1, 0><<<ge2, 256>>>(p_hidden, enc_w2, enc_b2, p_m, N_AG, 64, 128,
                                  nullptr, nullptr, nullptr, nullptr, 0);
    k_yagg<<<(N_AG * 32 + 255) / 256, 256>>>();
    k_mma<128, 0, 1><<<ggru, 256>>>(p_xcat, gru_w_ih, gru_b_ih, p_gi, N_AG, 384, 192,
                                    p_h, gru_w_hh, gru_b_hh, p_gh, 128);
    k_gru<<<gru_grid, 256>>>(p_h);

    k_out<<<(N_AG * 32 + 255) / 256, 256>>>(out_w, out_b, out, write_zz);
}